// round 3
// baseline (speedup 1.0000x reference)
#include <cuda_runtime.h>

#define NG   4
#define NB   4
#define LQ   512
#define NC   768
#define NH   12
#define DH   64
#define MPG  (NB*LQ)           // 2048 rows per group

// Scratch: Q/K/V in head-major layout [((g*NB+b)*NH+h)*LQ + l]*DH + dh
__device__ float g_q[NG*NB*NH*LQ*DH];
__device__ float g_k[NG*NB*NH*LQ*DH];
__device__ float g_v[NG*NB*NH*LQ*DH];

// ---------------------------------------------------------------------------
// QKV projection GEMM: out[g, t, d] = hs[g, t, :] . W[g, :, d] + bias[g, d]
// scattered into head-major layout. 64x64 tile, k-chunk 16, 4x4 microtile.
// grid = (NC/64, MPG/64, NG), block = 256
// ---------------------------------------------------------------------------
__global__ __launch_bounds__(256) void qkv_gemm_kernel(
    const float* __restrict__ hs, const float* __restrict__ W,
    const float* __restrict__ bias, float* __restrict__ outp)
{
    __shared__ float As[64 * 16];
    __shared__ float Bs[16 * 64];

    const int g  = blockIdx.z;
    const int m0 = blockIdx.y * 64;
    const int n0 = blockIdx.x * 64;
    const int tid = threadIdx.x;
    const int tx = tid & 15;        // 0..15 -> 4 output cols each
    const int ty = tid >> 4;        // 0..15 -> 4 output rows each

    const float* hsg = hs + (size_t)g * MPG * NC;
    const float* Wg  = W  + (size_t)g * NC * NC;

    float4 acc[4];
    #pragma unroll
    for (int i = 0; i < 4; i++) acc[i] = make_float4(0.f, 0.f, 0.f, 0.f);

    for (int k0 = 0; k0 < NC; k0 += 16) {
        // A tile 64x16 (one float4 per thread, fully coalesced)
        {
            const int r  = tid >> 2;
            const int c4 = (tid & 3) * 4;
            *(float4*)(As + r * 16 + c4) =
                *(const float4*)(hsg + (size_t)(m0 + r) * NC + k0 + c4);
        }
        // B tile 16x64 (one float4 per thread, fully coalesced)
        {
            const int r  = tid >> 4;
            const int c4 = (tid & 15) * 4;
            *(float4*)(Bs + r * 64 + c4) =
                *(const float4*)(Wg + (size_t)(k0 + r) * NC + n0 + c4);
        }
        __syncthreads();

        #pragma unroll
        for (int kk = 0; kk < 16; kk++) {
            const float4 b = *(const float4*)(Bs + kk * 64 + tx * 4);
            #pragma unroll
            for (int ii = 0; ii < 4; ii++) {
                const float a = As[(ty * 4 + ii) * 16 + kk];
                acc[ii].x += a * b.x;
                acc[ii].y += a * b.y;
                acc[ii].z += a * b.z;
                acc[ii].w += a * b.w;
            }
        }
        __syncthreads();
    }

    // epilogue: add bias, scatter to head-major layout
    const float* bg = bias + (size_t)g * NC;
    #pragma unroll
    for (int ii = 0; ii < 4; ii++) {
        const int t = m0 + ty * 4 + ii;
        const int b = t / LQ;
        const int l = t % LQ;
        const float* av = (const float*)&acc[ii];
        #pragma unroll
        for (int jj = 0; jj < 4; jj++) {
            const int d  = n0 + tx * 4 + jj;
            const int h  = d / DH;
            const int dh = d % DH;
            outp[((((size_t)g * NB + b) * NH + h) * LQ + l) * DH + dh] =
                av[jj] + bg[d];
        }
    }
}

// ---------------------------------------------------------------------------
// Attention: one block per (gbh, 32-row query tile). block = 256 (8 warps).
// smem: Qs[32][64] | S[32][512] | KV[64][65] (K transposed+padded / V natural)
// ---------------------------------------------------------------------------
#define QT 32
#define SMEM_FLOATS (QT*DH + QT*LQ + 64*65)   // 22592 floats = 90368 B

__global__ __launch_bounds__(256) void attn_kernel(
    const float* __restrict__ qg, const float* __restrict__ kg,
    const float* __restrict__ vg, const float* __restrict__ mask,
    float* __restrict__ out)
{
    extern __shared__ float smem[];
    float* Qs = smem;                // [QT][DH]
    float* S  = smem + QT * DH;      // [QT][LQ]
    float* KV = S + QT * LQ;         // [64][65] (K) or [64][64] (V)

    const int gbh = blockIdx.y;          // ((g*NB+b)*NH + h)
    const int l0  = blockIdx.x * QT;
    const int h   = gbh % NH;
    const int gb  = gbh / NH;            // g*NB + b
    const int tid  = threadIdx.x;
    const int lane = tid & 31;
    const int warp = tid >> 5;           // 0..7 -> 4 query rows each

    const float* Q  = qg + (size_t)gbh * LQ * DH;
    const float* K  = kg + (size_t)gbh * LQ * DH;
    const float* V  = vg + (size_t)gbh * LQ * DH;
    const float* mk = mask + (size_t)gb * LQ;

    // load Q tile (natural layout)
    for (int idx = tid; idx < QT * DH; idx += 256)
        Qs[idx] = Q[(size_t)l0 * DH + idx];

    const float scale = 0.125f;   // 1/sqrt(64)

    // ---- phase 1: S[i][m] = Q[i].K[m]  (raw, scale applied in softmax) ----
    for (int kt = 0; kt < LQ / 64; kt++) {
        const int m0k = kt * 64;
        __syncthreads();                       // also covers Qs on first iter
        // K tile transposed: KV[c*65 + m] = K[m0k+m][c]
        for (int idx = tid; idx < 64 * 64; idx += 256) {
            const int m = idx >> 6, c = idx & 63;
            KV[c * 65 + m] = K[(size_t)(m0k + m) * DH + c];
        }
        __syncthreads();

        float acc[4][2];
        #pragma unroll
        for (int ii = 0; ii < 4; ii++) { acc[ii][0] = 0.f; acc[ii][1] = 0.f; }

        #pragma unroll 8
        for (int c = 0; c < 64; c++) {
            const float k0v = KV[c * 65 + lane * 2 + 0];
            const float k1v = KV[c * 65 + lane * 2 + 1];
            #pragma unroll
            for (int ii = 0; ii < 4; ii++) {
                const float qv = Qs[(warp * 4 + ii) * DH + c];  // warp broadcast
                acc[ii][0] += qv * k0v;
                acc[ii][1] += qv * k1v;
            }
        }
        #pragma unroll
        for (int ii = 0; ii < 4; ii++) {
            S[(warp * 4 + ii) * LQ + m0k + lane * 2 + 0] = acc[ii][0];
            S[(warp * 4 + ii) * LQ + m0k + lane * 2 + 1] = acc[ii][1];
        }
    }
    __syncthreads();

    // ---- phase 2: softmax per row (warp handles 4 rows) ----
    #pragma unroll
    for (int rr = 0; rr < 4; rr++) {
        float* Sr = S + (warp * 4 + rr) * LQ;
        float mx = -1e30f;
        for (int j = lane; j < LQ; j += 32) {
            const float v = Sr[j] * scale + mk[j];
            Sr[j] = v;
            mx = fmaxf(mx, v);
        }
        #pragma unroll
        for (int o = 16; o; o >>= 1) mx = fmaxf(mx, __shfl_xor_sync(0xFFFFFFFFu, mx, o));
        float sum = 0.f;
        for (int j = lane; j < LQ; j += 32) {
            const float e = __expf(Sr[j] - mx);
            Sr[j] = e;
            sum += e;
        }
        #pragma unroll
        for (int o = 16; o; o >>= 1) sum += __shfl_xor_sync(0xFFFFFFFFu, sum, o);
        const float inv = 1.0f / sum;
        for (int j = lane; j < LQ; j += 32) Sr[j] *= inv;
    }

    // ---- phase 3: ctx = P @ V ----
    float acc3[4][2];
    #pragma unroll
    for (int ii = 0; ii < 4; ii++) { acc3[ii][0] = 0.f; acc3[ii][1] = 0.f; }

    for (int kt = 0; kt < LQ / 64; kt++) {
        const int m0k = kt * 64;
        __syncthreads();
        // V tile natural layout [m][d]
        for (int idx = tid; idx < 64 * 64; idx += 256)
            KV[idx] = V[(size_t)m0k * DH + idx];
        __syncthreads();

        #pragma unroll 8
        for (int mm = 0; mm < 64; mm++) {
            const float v0 = KV[mm * 64 + lane * 2 + 0];
            const float v1 = KV[mm * 64 + lane * 2 + 1];
            #pragma unroll
            for (int ii = 0; ii < 4; ii++) {
                const float p = S[(warp * 4 + ii) * LQ + m0k + mm]; // broadcast
                acc3[ii][0] += p * v0;
                acc3[ii][1] += p * v1;
            }
        }
    }

    // write: out[gb, l, h*DH + dh]
    #pragma unroll
    for (int ii = 0; ii < 4; ii++) {
        const size_t row = ((size_t)gb * LQ + l0 + warp * 4 + ii) * NC + h * DH;
        out[row + lane * 2 + 0] = acc3[ii][0];
        out[row + lane * 2 + 1] = acc3[ii][1];
    }
}

// ---------------------------------------------------------------------------
extern "C" void kernel_launch(void* const* d_in, const int* in_sizes, int n_in,
                              void* d_out, int out_size)
{
    (void)in_sizes; (void)n_in; (void)out_size;
    const float* hs   = (const float*)d_in[0];
    const float* mask = (const float*)d_in[1];
    const float* qw   = (const float*)d_in[2];
    const float* qb   = (const float*)d_in[3];
    const float* kw   = (const float*)d_in[4];
    const float* kb   = (const float*)d_in[5];
    const float* vw   = (const float*)d_in[6];
    const float* vb   = (const float*)d_in[7];
    float* out = (float*)d_out;

    float *qp, *kp, *vp;
    cudaGetSymbolAddress((void**)&qp, g_q);
    cudaGetSymbolAddress((void**)&kp, g_k);
    cudaGetSymbolAddress((void**)&vp, g_v);

    dim3 ggrid(NC / 64, MPG / 64, NG);
    qkv_gemm_kernel<<<ggrid, 256>>>(hs, qw, qb, qp);
    qkv_gemm_kernel<<<ggrid, 256>>>(hs, kw, kb, kp);
    qkv_gemm_kernel<<<ggrid, 256>>>(hs, vw, vb, vp);

    const int smem_bytes = SMEM_FLOATS * (int)sizeof(float);
    cudaFuncSetAttribute(attn_kernel,
                         cudaFuncAttributeMaxDynamicSharedMemorySize, smem_bytes);
    dim3 agrid(LQ / QT, NG * NB * NH);
    attn_kernel<<<agrid, 256, smem_bytes>>>(qp, kp, vp, mask, out);
}

// round 4
// speedup vs baseline: 1.0023x; 1.0023x over previous
#include <cuda_runtime.h>

#define NG   4
#define NB   4
#define LQ   512
#define NC   768
#define NH   12
#define DH   64
#define MPG  (NB*LQ)           // 2048 rows per group

// Scratch: Q/K/V in head-major layout [((g*NB+b)*NH+h)*LQ + l]*DH + dh
__device__ float g_q[NG*NB*NH*LQ*DH];
__device__ float g_k[NG*NB*NH*LQ*DH];
__device__ float g_v[NG*NB*NH*LQ*DH];

// ---------------------------------------------------------------------------
// QKV projection GEMM: out[g, t, d] = hs[g, t, :] . W[g, :, d] + bias[g, d]
// scattered into head-major layout. 64x64 tile, k-chunk 16, 4x4 microtile.
// grid = (NC/64, MPG/64, NG), block = 256
// ---------------------------------------------------------------------------
__global__ __launch_bounds__(256) void qkv_gemm_kernel(
    const float* __restrict__ hs, const float* __restrict__ W,
    const float* __restrict__ bias, float* __restrict__ outp)
{
    __shared__ float As[64 * 16];
    __shared__ float Bs[16 * 64];

    const int g  = blockIdx.z;
    const int m0 = blockIdx.y * 64;
    const int n0 = blockIdx.x * 64;
    const int tid = threadIdx.x;
    const int tx = tid & 15;        // 0..15 -> 4 output cols each
    const int ty = tid >> 4;        // 0..15 -> 4 output rows each

    const float* hsg = hs + (size_t)g * MPG * NC;
    const float* Wg  = W  + (size_t)g * NC * NC;

    float4 acc[4];
    #pragma unroll
    for (int i = 0; i < 4; i++) acc[i] = make_float4(0.f, 0.f, 0.f, 0.f);

    for (int k0 = 0; k0 < NC; k0 += 16) {
        // A tile 64x16 (one float4 per thread, fully coalesced)
        {
            const int r  = tid >> 2;
            const int c4 = (tid & 3) * 4;
            *(float4*)(As + r * 16 + c4) =
                *(const float4*)(hsg + (size_t)(m0 + r) * NC + k0 + c4);
        }
        // B tile 16x64 (one float4 per thread, fully coalesced)
        {
            const int r  = tid >> 4;
            const int c4 = (tid & 15) * 4;
            *(float4*)(Bs + r * 64 + c4) =
                *(const float4*)(Wg + (size_t)(k0 + r) * NC + n0 + c4);
        }
        __syncthreads();

        #pragma unroll
        for (int kk = 0; kk < 16; kk++) {
            const float4 b = *(const float4*)(Bs + kk * 64 + tx * 4);
            #pragma unroll
            for (int ii = 0; ii < 4; ii++) {
                const float a = As[(ty * 4 + ii) * 16 + kk];
                acc[ii].x += a * b.x;
                acc[ii].y += a * b.y;
                acc[ii].z += a * b.z;
                acc[ii].w += a * b.w;
            }
        }
        __syncthreads();
    }

    // epilogue: add bias, scatter to head-major layout
    const float* bg = bias + (size_t)g * NC;
    #pragma unroll
    for (int ii = 0; ii < 4; ii++) {
        const int t = m0 + ty * 4 + ii;
        const int b = t / LQ;
        const int l = t % LQ;
        const float* av = (const float*)&acc[ii];
        #pragma unroll
        for (int jj = 0; jj < 4; jj++) {
            const int d  = n0 + tx * 4 + jj;
            const int h  = d / DH;
            const int dh = d % DH;
            outp[((((size_t)g * NB + b) * NH + h) * LQ + l) * DH + dh] =
                av[jj] + bg[d];
        }
    }
}

// ---------------------------------------------------------------------------
// Attention: one block per (gbh, 32-row query tile). block = 256 (8 warps).
// smem: Qs[32][64] | S[32][512] | KV[64][65] (K transposed+padded / V natural)
// ---------------------------------------------------------------------------
#define QT 32
#define SMEM_FLOATS (QT*DH + QT*LQ + 64*65)   // 22592 floats = 90368 B

__global__ __launch_bounds__(256) void attn_kernel(
    const float* __restrict__ qg, const float* __restrict__ kg,
    const float* __restrict__ vg, const float* __restrict__ mask,
    float* __restrict__ out)
{
    extern __shared__ float smem[];
    float* Qs = smem;                // [QT][DH]
    float* S  = smem + QT * DH;      // [QT][LQ]
    float* KV = S + QT * LQ;         // [64][65] (K) or [64][64] (V)

    const int gbh = blockIdx.y;          // ((g*NB+b)*NH + h)
    const int l0  = blockIdx.x * QT;
    const int h   = gbh % NH;
    const int gb  = gbh / NH;            // g*NB + b
    const int tid  = threadIdx.x;
    const int lane = tid & 31;
    const int warp = tid >> 5;           // 0..7 -> 4 query rows each

    const float* Q  = qg + (size_t)gbh * LQ * DH;
    const float* K  = kg + (size_t)gbh * LQ * DH;
    const float* V  = vg + (size_t)gbh * LQ * DH;
    const float* mk = mask + (size_t)gb * LQ;

    // load Q tile (natural layout)
    for (int idx = tid; idx < QT * DH; idx += 256)
        Qs[idx] = Q[(size_t)l0 * DH + idx];

    const float scale = 0.125f;   // 1/sqrt(64)

    // ---- phase 1: S[i][m] = Q[i].K[m]  (raw, scale applied in softmax) ----
    for (int kt = 0; kt < LQ / 64; kt++) {
        const int m0k = kt * 64;
        __syncthreads();                       // also covers Qs on first iter
        // K tile transposed: KV[c*65 + m] = K[m0k+m][c]
        for (int idx = tid; idx < 64 * 64; idx += 256) {
            const int m = idx >> 6, c = idx & 63;
            KV[c * 65 + m] = K[(size_t)(m0k + m) * DH + c];
        }
        __syncthreads();

        float acc[4][2];
        #pragma unroll
        for (int ii = 0; ii < 4; ii++) { acc[ii][0] = 0.f; acc[ii][1] = 0.f; }

        #pragma unroll 8
        for (int c = 0; c < 64; c++) {
            const float k0v = KV[c * 65 + lane * 2 + 0];
            const float k1v = KV[c * 65 + lane * 2 + 1];
            #pragma unroll
            for (int ii = 0; ii < 4; ii++) {
                const float qv = Qs[(warp * 4 + ii) * DH + c];  // warp broadcast
                acc[ii][0] += qv * k0v;
                acc[ii][1] += qv * k1v;
            }
        }
        #pragma unroll
        for (int ii = 0; ii < 4; ii++) {
            S[(warp * 4 + ii) * LQ + m0k + lane * 2 + 0] = acc[ii][0];
            S[(warp * 4 + ii) * LQ + m0k + lane * 2 + 1] = acc[ii][1];
        }
    }
    __syncthreads();

    // ---- phase 2: softmax per row (warp handles 4 rows) ----
    #pragma unroll
    for (int rr = 0; rr < 4; rr++) {
        float* Sr = S + (warp * 4 + rr) * LQ;
        float mx = -1e30f;
        for (int j = lane; j < LQ; j += 32) {
            const float v = Sr[j] * scale + mk[j];
            Sr[j] = v;
            mx = fmaxf(mx, v);
        }
        #pragma unroll
        for (int o = 16; o; o >>= 1) mx = fmaxf(mx, __shfl_xor_sync(0xFFFFFFFFu, mx, o));
        float sum = 0.f;
        for (int j = lane; j < LQ; j += 32) {
            const float e = __expf(Sr[j] - mx);
            Sr[j] = e;
            sum += e;
        }
        #pragma unroll
        for (int o = 16; o; o >>= 1) sum += __shfl_xor_sync(0xFFFFFFFFu, sum, o);
        const float inv = 1.0f / sum;
        for (int j = lane; j < LQ; j += 32) Sr[j] *= inv;
    }

    // ---- phase 3: ctx = P @ V ----
    float acc3[4][2];
    #pragma unroll
    for (int ii = 0; ii < 4; ii++) { acc3[ii][0] = 0.f; acc3[ii][1] = 0.f; }

    for (int kt = 0; kt < LQ / 64; kt++) {
        const int m0k = kt * 64;
        __syncthreads();
        // V tile natural layout [m][d]
        for (int idx = tid; idx < 64 * 64; idx += 256)
            KV[idx] = V[(size_t)m0k * DH + idx];
        __syncthreads();

        #pragma unroll 8
        for (int mm = 0; mm < 64; mm++) {
            const float v0 = KV[mm * 64 + lane * 2 + 0];
            const float v1 = KV[mm * 64 + lane * 2 + 1];
            #pragma unroll
            for (int ii = 0; ii < 4; ii++) {
                const float p = S[(warp * 4 + ii) * LQ + m0k + mm]; // broadcast
                acc3[ii][0] += p * v0;
                acc3[ii][1] += p * v1;
            }
        }
    }

    // write: out[gb, l, h*DH + dh]
    #pragma unroll
    for (int ii = 0; ii < 4; ii++) {
        const size_t row = ((size_t)gb * LQ + l0 + warp * 4 + ii) * NC + h * DH;
        out[row + lane * 2 + 0] = acc3[ii][0];
        out[row + lane * 2 + 1] = acc3[ii][1];
    }
}

// ---------------------------------------------------------------------------
extern "C" void kernel_launch(void* const* d_in, const int* in_sizes, int n_in,
                              void* d_out, int out_size)
{
    (void)in_sizes; (void)n_in; (void)out_size;
    const float* hs   = (const float*)d_in[0];
    const float* mask = (const float*)d_in[1];
    const float* qw   = (const float*)d_in[2];
    const float* qb   = (const float*)d_in[3];
    const float* kw   = (const float*)d_in[4];
    const float* kb   = (const float*)d_in[5];
    const float* vw   = (const float*)d_in[6];
    const float* vb   = (const float*)d_in[7];
    float* out = (float*)d_out;

    float *qp, *kp, *vp;
    cudaGetSymbolAddress((void**)&qp, g_q);
    cudaGetSymbolAddress((void**)&kp, g_k);
    cudaGetSymbolAddress((void**)&vp, g_v);

    dim3 ggrid(NC / 64, MPG / 64, NG);
    qkv_gemm_kernel<<<ggrid, 256>>>(hs, qw, qb, qp);
    qkv_gemm_kernel<<<ggrid, 256>>>(hs, kw, kb, kp);
    qkv_gemm_kernel<<<ggrid, 256>>>(hs, vw, vb, vp);

    const int smem_bytes = SMEM_FLOATS * (int)sizeof(float);
    cudaFuncSetAttribute(attn_kernel,
                         cudaFuncAttributeMaxDynamicSharedMemorySize, smem_bytes);
    dim3 agrid(LQ / QT, NG * NB * NH);
    attn_kernel<<<agrid, 256, smem_bytes>>>(qp, kp, vp, mask, out);
}

// round 6
// speedup vs baseline: 1.5069x; 1.5034x over previous
#include <cuda_runtime.h>
#include <cstdint>

#define NG   4
#define NB   4
#define LQ   512
#define NC   768
#define NH   12
#define DH   64
#define MPG  (NB*LQ)           // 2048 rows per group

// Scratch: Q/K/V in head-major layout [((g*NB+b)*NH+h)*LQ + l]*DH + dh
__device__ float g_q[NG*NB*NH*LQ*DH];
__device__ float g_k[NG*NB*NH*LQ*DH];
__device__ float g_v[NG*NB*NH*LQ*DH];
// Transposed weights: [which*4+g][768][768] (row n = W[:,n])
__device__ float g_wt[12*NC*NC];

__device__ __forceinline__ uint32_t f2tf(float f) {
    uint32_t u;
    asm("cvt.rna.tf32.f32 %0, %1;" : "=r"(u) : "f"(f));
    return u;
}

__device__ __forceinline__ void mma_tf32(float* d, const uint32_t* a, const uint32_t* b) {
    asm volatile(
        "mma.sync.aligned.m16n8k8.row.col.f32.tf32.tf32.f32 "
        "{%0,%1,%2,%3}, {%4,%5,%6,%7}, {%8,%9}, {%0,%1,%2,%3};"
        : "+f"(d[0]), "+f"(d[1]), "+f"(d[2]), "+f"(d[3])
        : "r"(a[0]), "r"(a[1]), "r"(a[2]), "r"(a[3]), "r"(b[0]), "r"(b[1]));
}

// ---------------------------------------------------------------------------
// Weight transpose: g_wt[w*4+g][n][k] = W_w,g[k][n].  grid (24,24,12), blk (32,8)
// ---------------------------------------------------------------------------
__global__ __launch_bounds__(256) void wt_transpose_kernel(
    const float* __restrict__ qw, const float* __restrict__ kw,
    const float* __restrict__ vw, float* __restrict__ wt)
{
    __shared__ float tile[32][33];
    const int which = blockIdx.z >> 2, g = blockIdx.z & 3;
    const float* W = (which == 0 ? qw : which == 1 ? kw : vw) + (size_t)g * NC * NC;
    float* WT = wt + (size_t)(which * 4 + g) * NC * NC;
    const int tx = threadIdx.x, ty = threadIdx.y;
    const int x = blockIdx.x * 32 + tx;
    const int y = blockIdx.y * 32 + ty;
    #pragma unroll
    for (int j = 0; j < 32; j += 8)
        tile[ty + j][tx] = W[(size_t)(y + j) * NC + x];
    __syncthreads();
    const int x2 = blockIdx.y * 32 + tx;
    const int y2 = blockIdx.x * 32 + ty;
    #pragma unroll
    for (int j = 0; j < 32; j += 8)
        WT[(size_t)(y2 + j) * NC + x2] = tile[tx][ty + j];
}

// ---------------------------------------------------------------------------
// tf32 mma.sync QKV projection. 128x128 CTA tile, 8 warps (64x32 each),
// K in 24 chunks of 32, register-prefetch double buffering.
// grid = (6, 16, 12), block = 256.
// ---------------------------------------------------------------------------
#define APAD 36
#define BUFF (128*APAD)

__global__ __launch_bounds__(256) void qkv_mma_kernel(
    const float* __restrict__ hs, const float* __restrict__ wt,
    const float* __restrict__ qb, const float* __restrict__ kb, const float* __restrict__ vb,
    float* __restrict__ qp, float* __restrict__ kp, float* __restrict__ vp)
{
    extern __shared__ float sm[];
    float* As = sm;               // [2][128][36]
    float* Bs = sm + 2 * BUFF;    // [2][128][36]

    const int which = blockIdx.z >> 2, g = blockIdx.z & 3;
    const int m0 = blockIdx.y * 128, n0 = blockIdx.x * 128;
    const int tid = threadIdx.x, lane = tid & 31, wid = tid >> 5;
    const int wm = wid & 1, wn = wid >> 1;       // warp tile: (wm*64, wn*32)
    const int gq = lane >> 2, tg = lane & 3;

    const float* Ag = hs + (size_t)g * MPG * NC + (size_t)m0 * NC;
    const float* Bg = wt + (size_t)(which * 4 + g) * NC * NC + (size_t)n0 * NC;
    const float* bg = (which == 0 ? qb : which == 1 ? kb : vb) + (size_t)g * NC;
    float*       op = (which == 0 ? qp : which == 1 ? kp : vp);

    float acc[4][4][4];
    #pragma unroll
    for (int i = 0; i < 4; i++)
        #pragma unroll
        for (int j = 0; j < 4; j++)
            #pragma unroll
            for (int q = 0; q < 4; q++) acc[i][j][q] = 0.f;

    const int lr = tid >> 3;      // 0..31 : row offset within 32-row slab
    const int lc = (tid & 7) * 4; // 0..28 : k column (float4)

    float4 pa[4], pb[4];
    // prologue: chunk 0 global -> regs -> smem buf 0
    #pragma unroll
    for (int i = 0; i < 4; i++) {
        pa[i] = *(const float4*)(Ag + (size_t)(i * 32 + lr) * NC + lc);
        pb[i] = *(const float4*)(Bg + (size_t)(i * 32 + lr) * NC + lc);
    }
    #pragma unroll
    for (int i = 0; i < 4; i++) {
        float* as = As + (i * 32 + lr) * APAD + lc;
        float* bs = Bs + (i * 32 + lr) * APAD + lc;
        as[0] = __uint_as_float(f2tf(pa[i].x)); as[1] = __uint_as_float(f2tf(pa[i].y));
        as[2] = __uint_as_float(f2tf(pa[i].z)); as[3] = __uint_as_float(f2tf(pa[i].w));
        bs[0] = __uint_as_float(f2tf(pb[i].x)); bs[1] = __uint_as_float(f2tf(pb[i].y));
        bs[2] = __uint_as_float(f2tf(pb[i].z)); bs[3] = __uint_as_float(f2tf(pb[i].w));
    }
    __syncthreads();

    const int NCH = NC / 32;     // 24
    for (int c = 0; c < NCH; c++) {
        const int buf = c & 1;
        if (c + 1 < NCH) {
            const int kc = (c + 1) * 32;
            #pragma unroll
            for (int i = 0; i < 4; i++) {
                pa[i] = *(const float4*)(Ag + (size_t)(i * 32 + lr) * NC + kc + lc);
                pb[i] = *(const float4*)(Bg + (size_t)(i * 32 + lr) * NC + kc + lc);
            }
        }
        // compute chunk c from smem[buf]
        {
            const float* Ab = As + buf * BUFF + (wm * 64) * APAD;
            const float* Bb = Bs + buf * BUFF + (wn * 32) * APAD;
            #pragma unroll
            for (int ks = 0; ks < 4; ks++) {
                const int kk = ks * 8;
                uint32_t af[4][4], bf[4][2];
                #pragma unroll
                for (int mt = 0; mt < 4; mt++) {
                    const float* ap = Ab + (mt * 16 + gq) * APAD + kk + tg;
                    af[mt][0] = __float_as_uint(ap[0]);
                    af[mt][1] = __float_as_uint(ap[8 * APAD]);
                    af[mt][2] = __float_as_uint(ap[4]);
                    af[mt][3] = __float_as_uint(ap[8 * APAD + 4]);
                }
                #pragma unroll
                for (int nt = 0; nt < 4; nt++) {
                    const float* bp = Bb + (nt * 8 + gq) * APAD + kk + tg;
                    bf[nt][0] = __float_as_uint(bp[0]);
                    bf[nt][1] = __float_as_uint(bp[4]);
                }
                #pragma unroll
                for (int mt = 0; mt < 4; mt++)
                    #pragma unroll
                    for (int nt = 0; nt < 4; nt++)
                        mma_tf32(acc[mt][nt], af[mt], bf[nt]);
            }
        }
        __syncthreads();
        if (c + 1 < NCH) {
            const int nb = buf ^ 1;
            #pragma unroll
            for (int i = 0; i < 4; i++) {
                float* as = As + nb * BUFF + (i * 32 + lr) * APAD + lc;
                float* bs = Bs + nb * BUFF + (i * 32 + lr) * APAD + lc;
                as[0] = __uint_as_float(f2tf(pa[i].x)); as[1] = __uint_as_float(f2tf(pa[i].y));
                as[2] = __uint_as_float(f2tf(pa[i].z)); as[3] = __uint_as_float(f2tf(pa[i].w));
                bs[0] = __uint_as_float(f2tf(pb[i].x)); bs[1] = __uint_as_float(f2tf(pb[i].y));
                bs[2] = __uint_as_float(f2tf(pb[i].z)); bs[3] = __uint_as_float(f2tf(pb[i].w));
            }
            __syncthreads();
        }
    }

    // epilogue: bias add + head-major scatter
    #pragma unroll
    for (int mt = 0; mt < 4; mt++) {
        const int row0 = m0 + wm * 64 + mt * 16 + gq;
        #pragma unroll
        for (int half = 0; half < 2; half++) {
            const int trow = row0 + half * 8;
            const int b = trow >> 9, l = trow & 511;
            #pragma unroll
            for (int nt = 0; nt < 4; nt++) {
                const int col = n0 + wn * 32 + nt * 8 + 2 * tg;
                const int h = col >> 6, dh = col & 63;
                const float2 bv = *(const float2*)(bg + col);
                float2 o;
                o.x = acc[mt][nt][half * 2 + 0] + bv.x;
                o.y = acc[mt][nt][half * 2 + 1] + bv.y;
                *(float2*)(op + ((((size_t)g * NB + b) * NH + h) * LQ + l) * DH + dh) = o;
            }
        }
    }
}

// ---------------------------------------------------------------------------
// Attention: one block per (gbh, 32-row query tile). block = 256 (8 warps).
// smem: Qs[32][64] | S[32][512] | KV[64][65]
// ---------------------------------------------------------------------------
#define QT 32
#define SMEM_FLOATS (QT*DH + QT*LQ + 64*65)   // 22592 floats = 90368 B

__global__ __launch_bounds__(256) void attn_kernel(
    const float* __restrict__ qg, const float* __restrict__ kg,
    const float* __restrict__ vg, const float* __restrict__ mask,
    float* __restrict__ out)
{
    extern __shared__ float smem[];
    float* Qs = smem;                // [QT][DH]
    float* S  = smem + QT * DH;      // [QT][LQ]
    float* KV = S + QT * LQ;         // [64][65] (K) or [64][64] (V)

    const int gbh = blockIdx.y;
    const int l0  = blockIdx.x * QT;
    const int h   = gbh % NH;
    const int gb  = gbh / NH;
    const int tid  = threadIdx.x;
    const int lane = tid & 31;
    const int warp = tid >> 5;

    const float* Q  = qg + (size_t)gbh * LQ * DH;
    const float* K  = kg + (size_t)gbh * LQ * DH;
    const float* V  = vg + (size_t)gbh * LQ * DH;
    const float* mk = mask + (size_t)gb * LQ;

    for (int idx = tid; idx < QT * DH; idx += 256)
        Qs[idx] = Q[(size_t)l0 * DH + idx];

    const float scale = 0.125f;

    for (int kt = 0; kt < LQ / 64; kt++) {
        const int m0k = kt * 64;
        __syncthreads();
        for (int idx = tid; idx < 64 * 64; idx += 256) {
            const int m = idx >> 6, c = idx & 63;
            KV[c * 65 + m] = K[(size_t)(m0k + m) * DH + c];
        }
        __syncthreads();

        float acc[4][2];
        #pragma unroll
        for (int ii = 0; ii < 4; ii++) { acc[ii][0] = 0.f; acc[ii][1] = 0.f; }

        #pragma unroll 8
        for (int c = 0; c < 64; c++) {
            const float k0v = KV[c * 65 + lane * 2 + 0];
            const float k1v = KV[c * 65 + lane * 2 + 1];
            #pragma unroll
            for (int ii = 0; ii < 4; ii++) {
                const float qv = Qs[(warp * 4 + ii) * DH + c];
                acc[ii][0] += qv * k0v;
                acc[ii][1] += qv * k1v;
            }
        }
        #pragma unroll
        for (int ii = 0; ii < 4; ii++) {
            S[(warp * 4 + ii) * LQ + m0k + lane * 2 + 0] = acc[ii][0];
            S[(warp * 4 + ii) * LQ + m0k + lane * 2 + 1] = acc[ii][1];
        }
    }
    __syncthreads();

    #pragma unroll
    for (int rr = 0; rr < 4; rr++) {
        float* Sr = S + (warp * 4 + rr) * LQ;
        float mx = -1e30f;
        for (int j = lane; j < LQ; j += 32) {
            const float v = Sr[j] * scale + mk[j];
            Sr[j] = v;
            mx = fmaxf(mx, v);
        }
        #pragma unroll
        for (int o = 16; o; o >>= 1) mx = fmaxf(mx, __shfl_xor_sync(0xFFFFFFFFu, mx, o));
        float sum = 0.f;
        for (int j = lane; j < LQ; j += 32) {
            const float e = __expf(Sr[j] - mx);
            Sr[j] = e;
            sum += e;
        }
        #pragma unroll
        for (int o = 16; o; o >>= 1) sum += __shfl_xor_sync(0xFFFFFFFFu, sum, o);
        const float inv = 1.0f / sum;
        for (int j = lane; j < LQ; j += 32) Sr[j] *= inv;
    }

    float acc3[4][2];
    #pragma unroll
    for (int ii = 0; ii < 4; ii++) { acc3[ii][0] = 0.f; acc3[ii][1] = 0.f; }

    for (int kt = 0; kt < LQ / 64; kt++) {
        const int m0k = kt * 64;
        __syncthreads();
        for (int idx = tid; idx < 64 * 64; idx += 256)
            KV[idx] = V[(size_t)m0k * DH + idx];
        __syncthreads();

        #pragma unroll 8
        for (int mm = 0; mm < 64; mm++) {
            const float v0 = KV[mm * 64 + lane * 2 + 0];
            const float v1 = KV[mm * 64 + lane * 2 + 1];
            #pragma unroll
            for (int ii = 0; ii < 4; ii++) {
                const float p = S[(warp * 4 + ii) * LQ + m0k + mm];
                acc3[ii][0] += p * v0;
                acc3[ii][1] += p * v1;
            }
        }
    }

    #pragma unroll
    for (int ii = 0; ii < 4; ii++) {
        const size_t row = ((size_t)gb * LQ + l0 + warp * 4 + ii) * NC + h * DH;
        out[row + lane * 2 + 0] = acc3[ii][0];
        out[row + lane * 2 + 1] = acc3[ii][1];
    }
}

// ---------------------------------------------------------------------------
extern "C" void kernel_launch(void* const* d_in, const int* in_sizes, int n_in,
                              void* d_out, int out_size)
{
    (void)in_sizes; (void)n_in; (void)out_size;
    const float* hs   = (const float*)d_in[0];
    const float* mask = (const float*)d_in[1];
    const float* qw   = (const float*)d_in[2];
    const float* qb   = (const float*)d_in[3];
    const float* kw   = (const float*)d_in[4];
    const float* kb   = (const float*)d_in[5];
    const float* vw   = (const float*)d_in[6];
    const float* vb   = (const float*)d_in[7];
    float* out = (float*)d_out;

    float *qp, *kp, *vp, *wtp;
    cudaGetSymbolAddress((void**)&qp, g_q);
    cudaGetSymbolAddress((void**)&kp, g_k);
    cudaGetSymbolAddress((void**)&vp, g_v);
    cudaGetSymbolAddress((void**)&wtp, g_wt);

    dim3 tgrid(NC / 32, NC / 32, 12);
    wt_transpose_kernel<<<tgrid, dim3(32, 8)>>>(qw, kw, vw, wtp);

    const int gsmem = 4 * BUFF * (int)sizeof(float);   // 73728
    cudaFuncSetAttribute(qkv_mma_kernel,
                         cudaFuncAttributeMaxDynamicSharedMemorySize, gsmem);
    dim3 ggrid(NC / 128, MPG / 128, 12);
    qkv_mma_kernel<<<ggrid, 256, gsmem>>>(hs, wtp, qb, kb, vb, qp, kp, vp);

    const int smem_bytes = SMEM_FLOATS * (int)sizeof(float);
    cudaFuncSetAttribute(attn_kernel,
                         cudaFuncAttributeMaxDynamicSharedMemorySize, smem_bytes);
    dim3 agrid(LQ / QT, NG * NB * NH);
    attn_kernel<<<agrid, 256, smem_bytes>>>(qp, kp, vp, mask, out);
}

// round 7
// speedup vs baseline: 2.2238x; 1.4758x over previous
#include <cuda_runtime.h>
#include <cstdint>

#define NG   4
#define NB   4
#define LQ   512
#define NC   768
#define NH   12
#define DH   64
#define MPG  (NB*LQ)           // 2048 rows per group

// Scratch: Q/K/V in head-major layout [((g*NB+b)*NH+h)*LQ + l]*DH + dh
__device__ float g_q[NG*NB*NH*LQ*DH];
__device__ float g_k[NG*NB*NH*LQ*DH];
__device__ float g_v[NG*NB*NH*LQ*DH];
// Transposed weights: [which*4+g][768][768] (row n = W[:,n])
__device__ float g_wt[12*NC*NC];

__device__ __forceinline__ uint32_t f2tf(float f) {
    uint32_t u;
    asm("cvt.rna.tf32.f32 %0, %1;" : "=r"(u) : "f"(f));
    return u;
}
__device__ __forceinline__ float tf(float f) { return __uint_as_float(f2tf(f)); }

__device__ __forceinline__ void mma_tf32(float* d, const uint32_t* a, const uint32_t* b) {
    asm volatile(
        "mma.sync.aligned.m16n8k8.row.col.f32.tf32.tf32.f32 "
        "{%0,%1,%2,%3}, {%4,%5,%6,%7}, {%8,%9}, {%0,%1,%2,%3};"
        : "+f"(d[0]), "+f"(d[1]), "+f"(d[2]), "+f"(d[3])
        : "r"(a[0]), "r"(a[1]), "r"(a[2]), "r"(a[3]), "r"(b[0]), "r"(b[1]));
}

// FMA-pipe exp (avoids MUFU throughput ceiling). rel err ~2e-6.
__device__ __forceinline__ float fast_exp(float x) {
    float t = x * 1.4426950408889634f;
    t = fmaxf(t, -120.0f);
    const int  ei = __float2int_rn(t);
    const float f = t - (float)ei;
    float p =        1.3333558146e-3f;
    p = fmaf(p, f,   9.6181291076e-3f);
    p = fmaf(p, f,   5.5504108664e-2f);
    p = fmaf(p, f,   2.4022650695e-1f);
    p = fmaf(p, f,   6.9314718056e-1f);
    p = fmaf(p, f,   1.0f);
    return p * __int_as_float((ei + 127) << 23);
}

// ---------------------------------------------------------------------------
// Weight transpose: g_wt[w*4+g][n][k] = W_w,g[k][n].  grid (24,24,12), blk (32,8)
// ---------------------------------------------------------------------------
__global__ __launch_bounds__(256) void wt_transpose_kernel(
    const float* __restrict__ qw, const float* __restrict__ kw,
    const float* __restrict__ vw, float* __restrict__ wt)
{
    __shared__ float tile[32][33];
    const int which = blockIdx.z >> 2, g = blockIdx.z & 3;
    const float* W = (which == 0 ? qw : which == 1 ? kw : vw) + (size_t)g * NC * NC;
    float* WT = wt + (size_t)(which * 4 + g) * NC * NC;
    const int tx = threadIdx.x, ty = threadIdx.y;
    const int x = blockIdx.x * 32 + tx;
    const int y = blockIdx.y * 32 + ty;
    #pragma unroll
    for (int j = 0; j < 32; j += 8)
        tile[ty + j][tx] = W[(size_t)(y + j) * NC + x];
    __syncthreads();
    const int x2 = blockIdx.y * 32 + tx;
    const int y2 = blockIdx.x * 32 + ty;
    #pragma unroll
    for (int j = 0; j < 32; j += 8)
        WT[(size_t)(y2 + j) * NC + x2] = tile[tx][ty + j];
}

// ---------------------------------------------------------------------------
// tf32 mma.sync QKV projection (unchanged from R5).
// ---------------------------------------------------------------------------
#define APAD 36
#define BUFF (128*APAD)

__global__ __launch_bounds__(256) void qkv_mma_kernel(
    const float* __restrict__ hs, const float* __restrict__ wt,
    const float* __restrict__ qb, const float* __restrict__ kb, const float* __restrict__ vb,
    float* __restrict__ qp, float* __restrict__ kp, float* __restrict__ vp)
{
    extern __shared__ float sm[];
    float* As = sm;               // [2][128][36]
    float* Bs = sm + 2 * BUFF;    // [2][128][36]

    const int which = blockIdx.z >> 2, g = blockIdx.z & 3;
    const int m0 = blockIdx.y * 128, n0 = blockIdx.x * 128;
    const int tid = threadIdx.x, lane = tid & 31, wid = tid >> 5;
    const int wm = wid & 1, wn = wid >> 1;
    const int gq = lane >> 2, tg = lane & 3;

    const float* Ag = hs + (size_t)g * MPG * NC + (size_t)m0 * NC;
    const float* Bg = wt + (size_t)(which * 4 + g) * NC * NC + (size_t)n0 * NC;
    const float* bg = (which == 0 ? qb : which == 1 ? kb : vb) + (size_t)g * NC;
    float*       op = (which == 0 ? qp : which == 1 ? kp : vp);

    float acc[4][4][4];
    #pragma unroll
    for (int i = 0; i < 4; i++)
        #pragma unroll
        for (int j = 0; j < 4; j++)
            #pragma unroll
            for (int q = 0; q < 4; q++) acc[i][j][q] = 0.f;

    const int lr = tid >> 3;
    const int lc = (tid & 7) * 4;

    float4 pa[4], pb[4];
    #pragma unroll
    for (int i = 0; i < 4; i++) {
        pa[i] = *(const float4*)(Ag + (size_t)(i * 32 + lr) * NC + lc);
        pb[i] = *(const float4*)(Bg + (size_t)(i * 32 + lr) * NC + lc);
    }
    #pragma unroll
    for (int i = 0; i < 4; i++) {
        float* as = As + (i * 32 + lr) * APAD + lc;
        float* bs = Bs + (i * 32 + lr) * APAD + lc;
        as[0] = tf(pa[i].x); as[1] = tf(pa[i].y); as[2] = tf(pa[i].z); as[3] = tf(pa[i].w);
        bs[0] = tf(pb[i].x); bs[1] = tf(pb[i].y); bs[2] = tf(pb[i].z); bs[3] = tf(pb[i].w);
    }
    __syncthreads();

    const int NCH = NC / 32;
    for (int c = 0; c < NCH; c++) {
        const int buf = c & 1;
        if (c + 1 < NCH) {
            const int kc = (c + 1) * 32;
            #pragma unroll
            for (int i = 0; i < 4; i++) {
                pa[i] = *(const float4*)(Ag + (size_t)(i * 32 + lr) * NC + kc + lc);
                pb[i] = *(const float4*)(Bg + (size_t)(i * 32 + lr) * NC + kc + lc);
            }
        }
        {
            const float* Ab = As + buf * BUFF + (wm * 64) * APAD;
            const float* Bb = Bs + buf * BUFF + (wn * 32) * APAD;
            #pragma unroll
            for (int ks = 0; ks < 4; ks++) {
                const int kk = ks * 8;
                uint32_t af[4][4], bf[4][2];
                #pragma unroll
                for (int mt = 0; mt < 4; mt++) {
                    const float* ap = Ab + (mt * 16 + gq) * APAD + kk + tg;
                    af[mt][0] = __float_as_uint(ap[0]);
                    af[mt][1] = __float_as_uint(ap[8 * APAD]);
                    af[mt][2] = __float_as_uint(ap[4]);
                    af[mt][3] = __float_as_uint(ap[8 * APAD + 4]);
                }
                #pragma unroll
                for (int nt = 0; nt < 4; nt++) {
                    const float* bp = Bb + (nt * 8 + gq) * APAD + kk + tg;
                    bf[nt][0] = __float_as_uint(bp[0]);
                    bf[nt][1] = __float_as_uint(bp[4]);
                }
                #pragma unroll
                for (int mt = 0; mt < 4; mt++)
                    #pragma unroll
                    for (int nt = 0; nt < 4; nt++)
                        mma_tf32(acc[mt][nt], af[mt], bf[nt]);
            }
        }
        __syncthreads();
        if (c + 1 < NCH) {
            const int nb = buf ^ 1;
            #pragma unroll
            for (int i = 0; i < 4; i++) {
                float* as = As + nb * BUFF + (i * 32 + lr) * APAD + lc;
                float* bs = Bs + nb * BUFF + (i * 32 + lr) * APAD + lc;
                as[0] = tf(pa[i].x); as[1] = tf(pa[i].y); as[2] = tf(pa[i].z); as[3] = tf(pa[i].w);
                bs[0] = tf(pb[i].x); bs[1] = tf(pb[i].y); bs[2] = tf(pb[i].z); bs[3] = tf(pb[i].w);
            }
            __syncthreads();
        }
    }

    #pragma unroll
    for (int mt = 0; mt < 4; mt++) {
        const int row0 = m0 + wm * 64 + mt * 16 + gq;
        #pragma unroll
        for (int half = 0; half < 2; half++) {
            const int trow = row0 + half * 8;
            const int b = trow >> 9, l = trow & 511;
            #pragma unroll
            for (int nt = 0; nt < 4; nt++) {
                const int col = n0 + wn * 32 + nt * 8 + 2 * tg;
                const int h = col >> 6, dh = col & 63;
                const float2 bv = *(const float2*)(bg + col);
                float2 o;
                o.x = acc[mt][nt][half * 2 + 0] + bv.x;
                o.y = acc[mt][nt][half * 2 + 1] + bv.y;
                *(float2*)(op + ((((size_t)g * NB + b) * NH + h) * LQ + l) * DH + dh) = o;
            }
        }
    }
}

// ---------------------------------------------------------------------------
// tf32 mma.sync attention. One CTA per (gbh, 32-query tile). 256 thr (8 warps).
// smem: Qs[32][68] tf32 | S[32][516] | KV[2][64][68] tf32 | inv[32]
// Phase1: S = Q.K^T (warp w covers keys w*8 per 64-key chunk)
// Phase2: softmax -> unnormalized tf32 exp in S, 1/sum in inv[]
// Phase3: ctx = E.V (warp w covers dh slice w*8), scaled by inv in epilogue
// ---------------------------------------------------------------------------
#define QT    32
#define QPAD  68
#define SPAD  516
#define KPAD  68
#define ASM_FLOATS (QT*QPAD + QT*SPAD + 2*64*KPAD + 32)   // 27424 -> 109696 B

__global__ __launch_bounds__(256) void attn_mma_kernel(
    const float* __restrict__ qg, const float* __restrict__ kg,
    const float* __restrict__ vg, const float* __restrict__ mask,
    float* __restrict__ out)
{
    extern __shared__ float sm[];
    float* Qs  = sm;                       // [32][QPAD]
    float* S   = Qs + QT * QPAD;           // [32][SPAD]
    float* KVs = S + QT * SPAD;            // [2][64][KPAD]
    float* inv = KVs + 2 * 64 * KPAD;      // [32]

    const int gbh = blockIdx.y;
    const int l0  = blockIdx.x * QT;
    const int h   = gbh % NH;
    const int gb  = gbh / NH;
    const int tid  = threadIdx.x;
    const int lane = tid & 31;
    const int wid  = tid >> 5;
    const int gq = lane >> 2, tg = lane & 3;

    const float* Q  = qg + (size_t)gbh * LQ * DH;
    const float* K  = kg + (size_t)gbh * LQ * DH;
    const float* V  = vg + (size_t)gbh * LQ * DH;
    const float* mk = mask + (size_t)gb * LQ;

    // ---- load Q tile -> tf32 smem ----
    #pragma unroll
    for (int i = 0; i < 2; i++) {
        const int idx = i * 256 + tid;
        const int row = idx >> 4, c4 = (idx & 15) * 4;
        const float4 v = *(const float4*)(Q + (size_t)(l0 + row) * DH + c4);
        float* qs = Qs + row * QPAD + c4;
        qs[0] = tf(v.x); qs[1] = tf(v.y); qs[2] = tf(v.z); qs[3] = tf(v.w);
    }

    const int lkey = tid >> 2;            // 0..63 (chunk-load row)
    const int lc4  = (tid & 3) * 16;      // 0..48 (chunk-load col, x4 floats *4)

    float4 pf[4];
    // prologue: K chunk 0
    #pragma unroll
    for (int i = 0; i < 4; i++)
        pf[i] = *(const float4*)(K + (size_t)lkey * DH + lc4 + i * 4);
    #pragma unroll
    for (int i = 0; i < 4; i++) {
        float* ks = KVs + lkey * KPAD + lc4 + i * 4;
        ks[0] = tf(pf[i].x); ks[1] = tf(pf[i].y); ks[2] = tf(pf[i].z); ks[3] = tf(pf[i].w);
    }
    __syncthreads();   // also covers Qs

    // ---- phase 1: S = Q.K^T ----
    for (int c = 0; c < 8; c++) {
        if (c < 7) {
            const float* Kc = K + (size_t)(c + 1) * 64 * DH;
            #pragma unroll
            for (int i = 0; i < 4; i++)
                pf[i] = *(const float4*)(Kc + (size_t)lkey * DH + lc4 + i * 4);
        }
        {
            const float* Kb = KVs + (c & 1) * 64 * KPAD;
            float acc[2][4];
            #pragma unroll
            for (int mt = 0; mt < 2; mt++)
                #pragma unroll
                for (int q = 0; q < 4; q++) acc[mt][q] = 0.f;
            #pragma unroll
            for (int ks = 0; ks < 8; ks++) {
                const int kk = ks * 8;
                uint32_t af[2][4], bf[2];
                #pragma unroll
                for (int mt = 0; mt < 2; mt++) {
                    const float* ap = Qs + (mt * 16 + gq) * QPAD + kk + tg;
                    af[mt][0] = __float_as_uint(ap[0]);
                    af[mt][1] = __float_as_uint(ap[8 * QPAD]);
                    af[mt][2] = __float_as_uint(ap[4]);
                    af[mt][3] = __float_as_uint(ap[8 * QPAD + 4]);
                }
                const float* bp = Kb + (wid * 8 + gq) * KPAD + kk + tg;
                bf[0] = __float_as_uint(bp[0]);
                bf[1] = __float_as_uint(bp[4]);
                mma_tf32(acc[0], af[0], bf);
                mma_tf32(acc[1], af[1], bf);
            }
            const int col = c * 64 + wid * 8 + 2 * tg;
            #pragma unroll
            for (int mt = 0; mt < 2; mt++) {
                *(float2*)(S + (mt * 16 + gq) * SPAD + col)     = make_float2(acc[mt][0], acc[mt][1]);
                *(float2*)(S + (mt * 16 + gq + 8) * SPAD + col) = make_float2(acc[mt][2], acc[mt][3]);
            }
        }
        __syncthreads();
        if (c < 7) {
            float* ks = KVs + ((c + 1) & 1) * 64 * KPAD + lkey * KPAD + lc4;
            #pragma unroll
            for (int i = 0; i < 4; i++) {
                ks[i * 4 + 0] = tf(pf[i].x); ks[i * 4 + 1] = tf(pf[i].y);
                ks[i * 4 + 2] = tf(pf[i].z); ks[i * 4 + 3] = tf(pf[i].w);
            }
            __syncthreads();
        }
    }

    // ---- phase 2: softmax (unnormalized exp stored as tf32; 1/sum kept) ----
    const float scale = 0.125f;
    #pragma unroll
    for (int rr = 0; rr < 4; rr++) {
        const int row = wid * 4 + rr;
        float* Sr = S + row * SPAD;
        float mx = -1e30f;
        #pragma unroll 4
        for (int j = lane; j < LQ; j += 32)
            mx = fmaxf(mx, fmaf(Sr[j], scale, mk[j]));
        #pragma unroll
        for (int o = 16; o; o >>= 1) mx = fmaxf(mx, __shfl_xor_sync(0xFFFFFFFFu, mx, o));
        float sum = 0.f;
        #pragma unroll 4
        for (int j = lane; j < LQ; j += 32) {
            const float e = fast_exp(fmaf(Sr[j], scale, mk[j]) - mx);
            Sr[j] = tf(e);
            sum += e;
        }
        #pragma unroll
        for (int o = 16; o; o >>= 1) sum += __shfl_xor_sync(0xFFFFFFFFu, sum, o);
        if (lane == 0) inv[row] = 1.0f / sum;
    }

    // ---- phase 3: ctx = E.V ----
    float acc3[2][4];
    #pragma unroll
    for (int mt = 0; mt < 2; mt++)
        #pragma unroll
        for (int q = 0; q < 4; q++) acc3[mt][q] = 0.f;

    // prologue: V chunk 0
    #pragma unroll
    for (int i = 0; i < 4; i++)
        pf[i] = *(const float4*)(V + (size_t)lkey * DH + lc4 + i * 4);
    #pragma unroll
    for (int i = 0; i < 4; i++) {
        float* vs = KVs + lkey * KPAD + lc4 + i * 4;
        vs[0] = tf(pf[i].x); vs[1] = tf(pf[i].y); vs[2] = tf(pf[i].z); vs[3] = tf(pf[i].w);
    }
    __syncthreads();   // covers softmax S writes + inv too

    for (int c = 0; c < 8; c++) {
        if (c < 7) {
            const float* Vc = V + (size_t)(c + 1) * 64 * DH;
            #pragma unroll
            for (int i = 0; i < 4; i++)
                pf[i] = *(const float4*)(Vc + (size_t)lkey * DH + lc4 + i * 4);
        }
        {
            const float* Vb = KVs + (c & 1) * 64 * KPAD;
            #pragma unroll
            for (int ks = 0; ks < 8; ks++) {
                const int kk = ks * 8;
                uint32_t af[2][4], bf[2];
                #pragma unroll
                for (int mt = 0; mt < 2; mt++) {
                    const float* ap = S + (mt * 16 + gq) * SPAD + c * 64 + kk + tg;
                    af[mt][0] = __float_as_uint(ap[0]);
                    af[mt][1] = __float_as_uint(ap[8 * SPAD]);
                    af[mt][2] = __float_as_uint(ap[4]);
                    af[mt][3] = __float_as_uint(ap[8 * SPAD + 4]);
                }
                bf[0] = __float_as_uint(Vb[(kk + tg) * KPAD + wid * 8 + gq]);
                bf[1] = __float_as_uint(Vb[(kk + tg + 4) * KPAD + wid * 8 + gq]);
                mma_tf32(acc3[0], af[0], bf);
                mma_tf32(acc3[1], af[1], bf);
            }
        }
        __syncthreads();
        if (c < 7) {
            float* vs = KVs + ((c + 1) & 1) * 64 * KPAD + lkey * KPAD + lc4;
            #pragma unroll
            for (int i = 0; i < 4; i++) {
                vs[i * 4 + 0] = tf(pf[i].x); vs[i * 4 + 1] = tf(pf[i].y);
                vs[i * 4 + 2] = tf(pf[i].z); vs[i * 4 + 3] = tf(pf[i].w);
            }
            __syncthreads();
        }
    }

    // ---- epilogue: scale by 1/sum, write out ----
    #pragma unroll
    for (int mt = 0; mt < 2; mt++) {
        const int r0 = mt * 16 + gq;
        const float i0 = inv[r0], i1 = inv[r0 + 8];
        const int colo = h * DH + wid * 8 + 2 * tg;
        *(float2*)(out + ((size_t)gb * LQ + l0 + r0) * NC + colo) =
            make_float2(acc3[mt][0] * i0, acc3[mt][1] * i0);
        *(float2*)(out + ((size_t)gb * LQ + l0 + r0 + 8) * NC + colo) =
            make_float2(acc3[mt][2] * i1, acc3[mt][3] * i1);
    }
}

// ---------------------------------------------------------------------------
extern "C" void kernel_launch(void* const* d_in, const int* in_sizes, int n_in,
                              void* d_out, int out_size)
{
    (void)in_sizes; (void)n_in; (void)out_size;
    const float* hs   = (const float*)d_in[0];
    const float* mask = (const float*)d_in[1];
    const float* qw   = (const float*)d_in[2];
    const float* qb   = (const float*)d_in[3];
    const float* kw   = (const float*)d_in[4];
    const float* kb   = (const float*)d_in[5];
    const float* vw   = (const float*)d_in[6];
    const float* vb   = (const float*)d_in[7];
    float* out = (float*)d_out;

    float *qp, *kp, *vp, *wtp;
    cudaGetSymbolAddress((void**)&qp, g_q);
    cudaGetSymbolAddress((void**)&kp, g_k);
    cudaGetSymbolAddress((void**)&vp, g_v);
    cudaGetSymbolAddress((void**)&wtp, g_wt);

    dim3 tgrid(NC / 32, NC / 32, 12);
    wt_transpose_kernel<<<tgrid, dim3(32, 8)>>>(qw, kw, vw, wtp);

    const int gsmem = 4 * BUFF * (int)sizeof(float);   // 73728
    cudaFuncSetAttribute(qkv_mma_kernel,
                         cudaFuncAttributeMaxDynamicSharedMemorySize, gsmem);
    dim3 ggrid(NC / 128, MPG / 128, 12);
    qkv_mma_kernel<<<ggrid, 256, gsmem>>>(hs, wtp, qb, kb, vb, qp, kp, vp);

    const int asmem = ASM_FLOATS * (int)sizeof(float);  // 109696
    cudaFuncSetAttribute(attn_mma_kernel,
                         cudaFuncAttributeMaxDynamicSharedMemorySize, asmem);
    dim3 agrid(LQ / QT, NG * NB * NH);
    attn_mma_kernel<<<agrid, 256, asmem>>>(qp, kp, vp, mask, out);
}

// round 8
// speedup vs baseline: 2.4641x; 1.1081x over previous
#include <cuda_runtime.h>
#include <cstdint>

#define NG   4
#define NB   4
#define LQ   512
#define NC   768
#define NH   12
#define DH   64
#define MPG  (NB*LQ)           // 2048 rows per group

// Scratch: Q/K/V in head-major layout [((g*NB+b)*NH+h)*LQ + l]*DH + dh
__device__ float g_q[NG*NB*NH*LQ*DH];
__device__ float g_k[NG*NB*NH*LQ*DH];
__device__ float g_v[NG*NB*NH*LQ*DH];
// Transposed weights: [which*4+g][768][768] (row n = W[:,n])
__device__ float g_wt[12*NC*NC];

__device__ __forceinline__ uint32_t f2tf(float f) {
    uint32_t u;
    asm("cvt.rna.tf32.f32 %0, %1;" : "=r"(u) : "f"(f));
    return u;
}
__device__ __forceinline__ float tf(float f) { return __uint_as_float(f2tf(f)); }

__device__ __forceinline__ void mma_tf32(float* d, const uint32_t* a, const uint32_t* b) {
    asm volatile(
        "mma.sync.aligned.m16n8k8.row.col.f32.tf32.tf32.f32 "
        "{%0,%1,%2,%3}, {%4,%5,%6,%7}, {%8,%9}, {%0,%1,%2,%3};"
        : "+f"(d[0]), "+f"(d[1]), "+f"(d[2]), "+f"(d[3])
        : "r"(a[0]), "r"(a[1]), "r"(a[2]), "r"(a[3]), "r"(b[0]), "r"(b[1]));
}

// FMA-pipe exp (avoids MUFU throughput ceiling). rel err ~2e-6.
__device__ __forceinline__ float fast_exp(float x) {
    float t = x * 1.4426950408889634f;
    t = fmaxf(t, -120.0f);
    const int  ei = __float2int_rn(t);
    const float f = t - (float)ei;
    float p =        1.3333558146e-3f;
    p = fmaf(p, f,   9.6181291076e-3f);
    p = fmaf(p, f,   5.5504108664e-2f);
    p = fmaf(p, f,   2.4022650695e-1f);
    p = fmaf(p, f,   6.9314718056e-1f);
    p = fmaf(p, f,   1.0f);
    return p * __int_as_float((ei + 127) << 23);
}

// ---------------------------------------------------------------------------
// Weight transpose: g_wt[w*4+g][n][k] = W_w,g[k][n].  grid (24,24,12), blk (32,8)
// ---------------------------------------------------------------------------
__global__ __launch_bounds__(256) void wt_transpose_kernel(
    const float* __restrict__ qw, const float* __restrict__ kw,
    const float* __restrict__ vw, float* __restrict__ wt)
{
    __shared__ float tile[32][33];
    const int which = blockIdx.z >> 2, g = blockIdx.z & 3;
    const float* W = (which == 0 ? qw : which == 1 ? kw : vw) + (size_t)g * NC * NC;
    float* WT = wt + (size_t)(which * 4 + g) * NC * NC;
    const int tx = threadIdx.x, ty = threadIdx.y;
    const int x = blockIdx.x * 32 + tx;
    const int y = blockIdx.y * 32 + ty;
    #pragma unroll
    for (int j = 0; j < 32; j += 8)
        tile[ty + j][tx] = W[(size_t)(y + j) * NC + x];
    __syncthreads();
    const int x2 = blockIdx.y * 32 + tx;
    const int y2 = blockIdx.x * 32 + ty;
    #pragma unroll
    for (int j = 0; j < 32; j += 8)
        WT[(size_t)(y2 + j) * NC + x2] = tile[tx][ty + j];
}

// ---------------------------------------------------------------------------
// tf32 mma.sync QKV projection. 128x128 CTA tile, 8 warps (64x32 each),
// K in 24 chunks of 32, register-prefetch double buffering, 1 sync/chunk.
// grid = (6, 16, 12), block = 256.
// ---------------------------------------------------------------------------
#define APAD 36
#define BUFF (128*APAD)

__global__ __launch_bounds__(256) void qkv_mma_kernel(
    const float* __restrict__ hs, const float* __restrict__ wt,
    const float* __restrict__ qb, const float* __restrict__ kb, const float* __restrict__ vb,
    float* __restrict__ qp, float* __restrict__ kp, float* __restrict__ vp)
{
    extern __shared__ float sm[];
    float* As = sm;               // [2][128][36]
    float* Bs = sm + 2 * BUFF;    // [2][128][36]

    const int which = blockIdx.z >> 2, g = blockIdx.z & 3;
    const int m0 = blockIdx.y * 128, n0 = blockIdx.x * 128;
    const int tid = threadIdx.x, lane = tid & 31, wid = tid >> 5;
    const int wm = wid & 1, wn = wid >> 1;
    const int gq = lane >> 2, tg = lane & 3;

    const float* Ag = hs + (size_t)g * MPG * NC + (size_t)m0 * NC;
    const float* Bg = wt + (size_t)(which * 4 + g) * NC * NC + (size_t)n0 * NC;
    const float* bg = (which == 0 ? qb : which == 1 ? kb : vb) + (size_t)g * NC;
    float*       op = (which == 0 ? qp : which == 1 ? kp : vp);

    float acc[4][4][4];
    #pragma unroll
    for (int i = 0; i < 4; i++)
        #pragma unroll
        for (int j = 0; j < 4; j++)
            #pragma unroll
            for (int q = 0; q < 4; q++) acc[i][j][q] = 0.f;

    const int lr = tid >> 3;
    const int lc = (tid & 7) * 4;

    float4 pa[4], pb[4];
    #pragma unroll
    for (int i = 0; i < 4; i++) {
        pa[i] = *(const float4*)(Ag + (size_t)(i * 32 + lr) * NC + lc);
        pb[i] = *(const float4*)(Bg + (size_t)(i * 32 + lr) * NC + lc);
    }
    #pragma unroll
    for (int i = 0; i < 4; i++) {
        float* as = As + (i * 32 + lr) * APAD + lc;
        float* bs = Bs + (i * 32 + lr) * APAD + lc;
        as[0] = tf(pa[i].x); as[1] = tf(pa[i].y); as[2] = tf(pa[i].z); as[3] = tf(pa[i].w);
        bs[0] = tf(pb[i].x); bs[1] = tf(pb[i].y); bs[2] = tf(pb[i].z); bs[3] = tf(pb[i].w);
    }
    __syncthreads();

    const int NCH = NC / 32;
    for (int c = 0; c < NCH; c++) {
        const int buf = c & 1;
        if (c + 1 < NCH) {
            const int kc = (c + 1) * 32;
            #pragma unroll
            for (int i = 0; i < 4; i++) {
                pa[i] = *(const float4*)(Ag + (size_t)(i * 32 + lr) * NC + kc + lc);
                pb[i] = *(const float4*)(Bg + (size_t)(i * 32 + lr) * NC + kc + lc);
            }
        }
        {
            const float* Ab = As + buf * BUFF + (wm * 64) * APAD;
            const float* Bb = Bs + buf * BUFF + (wn * 32) * APAD;
            #pragma unroll
            for (int ks = 0; ks < 4; ks++) {
                const int kk = ks * 8;
                uint32_t af[4][4], bf[4][2];
                #pragma unroll
                for (int mt = 0; mt < 4; mt++) {
                    const float* ap = Ab + (mt * 16 + gq) * APAD + kk + tg;
                    af[mt][0] = __float_as_uint(ap[0]);
                    af[mt][1] = __float_as_uint(ap[8 * APAD]);
                    af[mt][2] = __float_as_uint(ap[4]);
                    af[mt][3] = __float_as_uint(ap[8 * APAD + 4]);
                }
                #pragma unroll
                for (int nt = 0; nt < 4; nt++) {
                    const float* bp = Bb + (nt * 8 + gq) * APAD + kk + tg;
                    bf[nt][0] = __float_as_uint(bp[0]);
                    bf[nt][1] = __float_as_uint(bp[4]);
                }
                #pragma unroll
                for (int mt = 0; mt < 4; mt++)
                    #pragma unroll
                    for (int nt = 0; nt < 4; nt++)
                        mma_tf32(acc[mt][nt], af[mt], bf[nt]);
            }
        }
        // store prefetched chunk into the other buffer; its last readers
        // (chunk c-1) finished before the sync at end of chunk c-1.
        if (c + 1 < NCH) {
            const int nb = buf ^ 1;
            #pragma unroll
            for (int i = 0; i < 4; i++) {
                float* as = As + nb * BUFF + (i * 32 + lr) * APAD + lc;
                float* bs = Bs + nb * BUFF + (i * 32 + lr) * APAD + lc;
                as[0] = tf(pa[i].x); as[1] = tf(pa[i].y); as[2] = tf(pa[i].z); as[3] = tf(pa[i].w);
                bs[0] = tf(pb[i].x); bs[1] = tf(pb[i].y); bs[2] = tf(pb[i].z); bs[3] = tf(pb[i].w);
            }
            __syncthreads();
        }
    }

    #pragma unroll
    for (int mt = 0; mt < 4; mt++) {
        const int row0 = m0 + wm * 64 + mt * 16 + gq;
        #pragma unroll
        for (int half = 0; half < 2; half++) {
            const int trow = row0 + half * 8;
            const int b = trow >> 9, l = trow & 511;
            #pragma unroll
            for (int nt = 0; nt < 4; nt++) {
                const int col = n0 + wn * 32 + nt * 8 + 2 * tg;
                const int h = col >> 6, dh = col & 63;
                const float2 bv = *(const float2*)(bg + col);
                float2 o;
                o.x = acc[mt][nt][half * 2 + 0] + bv.x;
                o.y = acc[mt][nt][half * 2 + 1] + bv.y;
                *(float2*)(op + ((((size_t)g * NB + b) * NH + h) * LQ + l) * DH + dh) = o;
            }
        }
    }
}

// ---------------------------------------------------------------------------
// tf32 mma.sync attention. One CTA per (gbh, 32-query tile). 256 thr (8 warps).
// smem: Qs[32][68] tf32 | S[32][516] | KV[2][64][68] tf32 | inv[32]
// Q fragments hoisted to registers; 1 sync per chunk.
// ---------------------------------------------------------------------------
#define QT    32
#define QPAD  68
#define SPAD  516
#define KPAD  68
#define ASM_FLOATS (QT*QPAD + QT*SPAD + 2*64*KPAD + 32)   // 27424 -> 109696 B

__global__ __launch_bounds__(256, 2) void attn_mma_kernel(
    const float* __restrict__ qg, const float* __restrict__ kg,
    const float* __restrict__ vg, const float* __restrict__ mask,
    float* __restrict__ out)
{
    extern __shared__ float sm[];
    float* Qs  = sm;                       // [32][QPAD]
    float* S   = Qs + QT * QPAD;           // [32][SPAD]
    float* KVs = S + QT * SPAD;            // [2][64][KPAD]
    float* inv = KVs + 2 * 64 * KPAD;      // [32]

    const int gbh = blockIdx.y;
    const int l0  = blockIdx.x * QT;
    const int h   = gbh % NH;
    const int gb  = gbh / NH;
    const int tid  = threadIdx.x;
    const int lane = tid & 31;
    const int wid  = tid >> 5;
    const int gq = lane >> 2, tg = lane & 3;

    const float* Q  = qg + (size_t)gbh * LQ * DH;
    const float* K  = kg + (size_t)gbh * LQ * DH;
    const float* V  = vg + (size_t)gbh * LQ * DH;
    const float* mk = mask + (size_t)gb * LQ;

    // ---- load Q tile -> tf32 smem ----
    #pragma unroll
    for (int i = 0; i < 2; i++) {
        const int idx = i * 256 + tid;
        const int row = idx >> 4, c4 = (idx & 15) * 4;
        const float4 v = *(const float4*)(Q + (size_t)(l0 + row) * DH + c4);
        float* qs = Qs + row * QPAD + c4;
        qs[0] = tf(v.x); qs[1] = tf(v.y); qs[2] = tf(v.z); qs[3] = tf(v.w);
    }

    const int lkey = tid >> 2;            // 0..63 (chunk-load row)
    const int lc4  = (tid & 3) * 16;      // 0..48 (chunk-load col)

    float4 pf[4];
    // prologue: K chunk 0
    #pragma unroll
    for (int i = 0; i < 4; i++)
        pf[i] = *(const float4*)(K + (size_t)lkey * DH + lc4 + i * 4);
    #pragma unroll
    for (int i = 0; i < 4; i++) {
        float* ks = KVs + lkey * KPAD + lc4 + i * 4;
        ks[0] = tf(pf[i].x); ks[1] = tf(pf[i].y); ks[2] = tf(pf[i].z); ks[3] = tf(pf[i].w);
    }
    __syncthreads();   // covers Qs + K chunk 0

    // ---- hoist Q fragments into registers (used by every phase-1 chunk) ----
    uint32_t qf[2][8][4];
    #pragma unroll
    for (int ks = 0; ks < 8; ks++) {
        const int kk = ks * 8;
        #pragma unroll
        for (int mt = 0; mt < 2; mt++) {
            const float* ap = Qs + (mt * 16 + gq) * QPAD + kk + tg;
            qf[mt][ks][0] = __float_as_uint(ap[0]);
            qf[mt][ks][1] = __float_as_uint(ap[8 * QPAD]);
            qf[mt][ks][2] = __float_as_uint(ap[4]);
            qf[mt][ks][3] = __float_as_uint(ap[8 * QPAD + 4]);
        }
    }

    // ---- phase 1: S = Q.K^T (1 sync per chunk) ----
    for (int c = 0; c < 8; c++) {
        if (c < 7) {
            const float* Kc = K + (size_t)(c + 1) * 64 * DH;
            #pragma unroll
            for (int i = 0; i < 4; i++)
                pf[i] = *(const float4*)(Kc + (size_t)lkey * DH + lc4 + i * 4);
        }
        {
            const float* Kb = KVs + (c & 1) * 64 * KPAD;
            float acc[2][4];
            #pragma unroll
            for (int mt = 0; mt < 2; mt++)
                #pragma unroll
                for (int q = 0; q < 4; q++) acc[mt][q] = 0.f;
            #pragma unroll
            for (int ks = 0; ks < 8; ks++) {
                const int kk = ks * 8;
                uint32_t bf[2];
                const float* bp = Kb + (wid * 8 + gq) * KPAD + kk + tg;
                bf[0] = __float_as_uint(bp[0]);
                bf[1] = __float_as_uint(bp[4]);
                mma_tf32(acc[0], qf[0][ks], bf);
                mma_tf32(acc[1], qf[1][ks], bf);
            }
            const int col = c * 64 + wid * 8 + 2 * tg;
            #pragma unroll
            for (int mt = 0; mt < 2; mt++) {
                *(float2*)(S + (mt * 16 + gq) * SPAD + col)     = make_float2(acc[mt][0], acc[mt][1]);
                *(float2*)(S + (mt * 16 + gq + 8) * SPAD + col) = make_float2(acc[mt][2], acc[mt][3]);
            }
        }
        if (c < 7) {
            float* ks = KVs + ((c + 1) & 1) * 64 * KPAD + lkey * KPAD + lc4;
            #pragma unroll
            for (int i = 0; i < 4; i++) {
                ks[i * 4 + 0] = tf(pf[i].x); ks[i * 4 + 1] = tf(pf[i].y);
                ks[i * 4 + 2] = tf(pf[i].z); ks[i * 4 + 3] = tf(pf[i].w);
            }
        }
        __syncthreads();
    }

    // ---- phase 2: softmax (scores cached in regs; S written once) ----
    const float scale = 0.125f;
    #pragma unroll
    for (int rr = 0; rr < 4; rr++) {
        const int row = wid * 4 + rr;
        float* Sr = S + row * SPAD;
        float t[16];
        float mx = -1e30f;
        #pragma unroll
        for (int jj = 0; jj < 16; jj++) {
            const int j = jj * 32 + lane;
            t[jj] = fmaf(Sr[j], scale, mk[j]);
            mx = fmaxf(mx, t[jj]);
        }
        #pragma unroll
        for (int o = 16; o; o >>= 1) mx = fmaxf(mx, __shfl_xor_sync(0xFFFFFFFFu, mx, o));
        float sum = 0.f;
        #pragma unroll
        for (int jj = 0; jj < 16; jj++) {
            const float e = fast_exp(t[jj] - mx);
            Sr[jj * 32 + lane] = tf(e);
            sum += e;
        }
        #pragma unroll
        for (int o = 16; o; o >>= 1) sum += __shfl_xor_sync(0xFFFFFFFFu, sum, o);
        if (lane == 0) inv[row] = 1.0f / sum;
    }

    // ---- phase 3: ctx = E.V ----
    float acc3[2][4];
    #pragma unroll
    for (int mt = 0; mt < 2; mt++)
        #pragma unroll
        for (int q = 0; q < 4; q++) acc3[mt][q] = 0.f;

    // prologue: V chunk 0 (buf0; phase-1 chunk 7 used buf1)
    #pragma unroll
    for (int i = 0; i < 4; i++)
        pf[i] = *(const float4*)(V + (size_t)lkey * DH + lc4 + i * 4);
    #pragma unroll
    for (int i = 0; i < 4; i++) {
        float* vs = KVs + lkey * KPAD + lc4 + i * 4;
        vs[0] = tf(pf[i].x); vs[1] = tf(pf[i].y); vs[2] = tf(pf[i].z); vs[3] = tf(pf[i].w);
    }
    __syncthreads();   // covers softmax S/inv writes + V chunk 0

    for (int c = 0; c < 8; c++) {
        if (c < 7) {
            const float* Vc = V + (size_t)(c + 1) * 64 * DH;
            #pragma unroll
            for (int i = 0; i < 4; i++)
                pf[i] = *(const float4*)(Vc + (size_t)lkey * DH + lc4 + i * 4);
        }
        {
            const float* Vb = KVs + (c & 1) * 64 * KPAD;
            #pragma unroll
            for (int ks = 0; ks < 8; ks++) {
                const int kk = ks * 8;
                uint32_t af[2][4], bf[2];
                #pragma unroll
                for (int mt = 0; mt < 2; mt++) {
                    const float* ap = S + (mt * 16 + gq) * SPAD + c * 64 + kk + tg;
                    af[mt][0] = __float_as_uint(ap[0]);
                    af[mt][1] = __float_as_uint(ap[8 * SPAD]);
                    af[mt][2] = __float_as_uint(ap[4]);
                    af[mt][3] = __float_as_uint(ap[8 * SPAD + 4]);
                }
                bf[0] = __float_as_uint(Vb[(kk + tg) * KPAD + wid * 8 + gq]);
                bf[1] = __float_as_uint(Vb[(kk + tg + 4) * KPAD + wid * 8 + gq]);
                mma_tf32(acc3[0], af[0], bf);
                mma_tf32(acc3[1], af[1], bf);
            }
        }
        if (c < 7) {
            float* vs = KVs + ((c + 1) & 1) * 64 * KPAD + lkey * KPAD + lc4;
            #pragma unroll
            for (int i = 0; i < 4; i++) {
                vs[i * 4 + 0] = tf(pf[i].x); vs[i * 4 + 1] = tf(pf[i].y);
                vs[i * 4 + 2] = tf(pf[i].z); vs[i * 4 + 3] = tf(pf[i].w);
            }
            __syncthreads();
        }
    }

    // ---- epilogue: scale by 1/sum, write out ----
    #pragma unroll
    for (int mt = 0; mt < 2; mt++) {
        const int r0 = mt * 16 + gq;
        const float i0 = inv[r0], i1 = inv[r0 + 8];
        const int colo = h * DH + wid * 8 + 2 * tg;
        *(float2*)(out + ((size_t)gb * LQ + l0 + r0) * NC + colo) =
            make_float2(acc3[mt][0] * i0, acc3[mt][1] * i0);
        *(float2*)(out + ((size_t)gb * LQ + l0 + r0 + 8) * NC + colo) =
            make_float2(acc3[mt][2] * i1, acc3[mt][3] * i1);
    }
}

// ---------------------------------------------------------------------------
extern "C" void kernel_launch(void* const* d_in, const int* in_sizes, int n_in,
                              void* d_out, int out_size)
{
    (void)in_sizes; (void)n_in; (void)out_size;
    const float* hs   = (const float*)d_in[0];
    const float* mask = (const float*)d_in[1];
    const float* qw   = (const float*)d_in[2];
    const float* qb   = (const float*)d_in[3];
    const float* kw   = (const float*)d_in[4];
    const float* kb   = (const float*)d_in[5];
    const float* vw   = (const float*)d_in[6];
    const float* vb   = (const float*)d_in[7];
    float* out = (float*)d_out;

    float *qp, *kp, *vp, *wtp;
    cudaGetSymbolAddress((void**)&qp, g_q);
    cudaGetSymbolAddress((void**)&kp, g_k);
    cudaGetSymbolAddress((void**)&vp, g_v);
    cudaGetSymbolAddress((void**)&wtp, g_wt);

    dim3 tgrid(NC / 32, NC / 32, 12);
    wt_transpose_kernel<<<tgrid, dim3(32, 8)>>>(qw, kw, vw, wtp);

    const int gsmem = 4 * BUFF * (int)sizeof(float);   // 73728
    cudaFuncSetAttribute(qkv_mma_kernel,
                         cudaFuncAttributeMaxDynamicSharedMemorySize, gsmem);
    dim3 ggrid(NC / 128, MPG / 128, 12);
    qkv_mma_kernel<<<ggrid, 256, gsmem>>>(hs, wtp, qb, kb, vb, qp, kp, vp);

    const int asmem = ASM_FLOATS * (int)sizeof(float);  // 109696
    cudaFuncSetAttribute(attn_mma_kernel,
                         cudaFuncAttributeMaxDynamicSharedMemorySize, asmem);
    dim3 agrid(LQ / QT, NG * NB * NH);
    attn_mma_kernel<<<agrid, 256, asmem>>>(qp, kp, vp, mask, out);
}

// round 9
// speedup vs baseline: 3.0788x; 1.2495x over previous
#include <cuda_runtime.h>
#include <cstdint>

#define NG   4
#define NB   4
#define LQ   512
#define NC   768
#define NH   12
#define DH   64
#define MPG  (NB*LQ)           // 2048 rows per group

// Scratch: Q/K/V in head-major layout [((g*NB+b)*NH+h)*LQ + l]*DH + dh
__device__ float g_q[NG*NB*NH*LQ*DH];
__device__ float g_k[NG*NB*NH*LQ*DH];
__device__ float g_v[NG*NB*NH*LQ*DH];
// Transposed weights: [which*4+g][768][768] (row n = W[:,n])
__device__ float g_wt[12*NC*NC];

__device__ __forceinline__ uint32_t f2tf(float f) {
    uint32_t u;
    asm("cvt.rna.tf32.f32 %0, %1;" : "=r"(u) : "f"(f));
    return u;
}
__device__ __forceinline__ float tf(float f) { return __uint_as_float(f2tf(f)); }

__device__ __forceinline__ void mma_tf32(float* d, const uint32_t* a, const uint32_t* b) {
    asm volatile(
        "mma.sync.aligned.m16n8k8.row.col.f32.tf32.tf32.f32 "
        "{%0,%1,%2,%3}, {%4,%5,%6,%7}, {%8,%9}, {%0,%1,%2,%3};"
        : "+f"(d[0]), "+f"(d[1]), "+f"(d[2]), "+f"(d[3])
        : "r"(a[0]), "r"(a[1]), "r"(a[2]), "r"(a[3]), "r"(b[0]), "r"(b[1]));
}

// FMA-pipe exp (avoids MUFU throughput ceiling). rel err ~2e-6.
__device__ __forceinline__ float fast_exp(float x) {
    float t = x * 1.4426950408889634f;
    t = fmaxf(t, -120.0f);
    const int  ei = __float2int_rn(t);
    const float f = t - (float)ei;
    float p =        1.3333558146e-3f;
    p = fmaf(p, f,   9.6181291076e-3f);
    p = fmaf(p, f,   5.5504108664e-2f);
    p = fmaf(p, f,   2.4022650695e-1f);
    p = fmaf(p, f,   6.9314718056e-1f);
    p = fmaf(p, f,   1.0f);
    return p * __int_as_float((ei + 127) << 23);
}

// ---------------------------------------------------------------------------
// Weight transpose: g_wt[w*4+g][n][k] = W_w,g[k][n].  grid (24,24,12), blk (32,8)
// ---------------------------------------------------------------------------
__global__ __launch_bounds__(256) void wt_transpose_kernel(
    const float* __restrict__ qw, const float* __restrict__ kw,
    const float* __restrict__ vw, float* __restrict__ wt)
{
    __shared__ float tile[32][33];
    const int which = blockIdx.z >> 2, g = blockIdx.z & 3;
    const float* W = (which == 0 ? qw : which == 1 ? kw : vw) + (size_t)g * NC * NC;
    float* WT = wt + (size_t)(which * 4 + g) * NC * NC;
    const int tx = threadIdx.x, ty = threadIdx.y;
    const int x = blockIdx.x * 32 + tx;
    const int y = blockIdx.y * 32 + ty;
    #pragma unroll
    for (int j = 0; j < 32; j += 8)
        tile[ty + j][tx] = W[(size_t)(y + j) * NC + x];
    __syncthreads();
    const int x2 = blockIdx.y * 32 + tx;
    const int y2 = blockIdx.x * 32 + ty;
    #pragma unroll
    for (int j = 0; j < 32; j += 8)
        WT[(size_t)(y2 + j) * NC + x2] = tile[tx][ty + j];
}

// ---------------------------------------------------------------------------
// tf32 mma.sync QKV projection. 128x128 CTA tile, 8 warps (64x32 each),
// K in 24 chunks of 32. Store-ahead pipeline: STS(next) before compute(cur)
// so the barrier never waits on a cold STS drain.
// grid = (6, 16, 12), block = 256.
// ---------------------------------------------------------------------------
#define APAD 36
#define BUFF (128*APAD)

__global__ __launch_bounds__(256) void qkv_mma_kernel(
    const float* __restrict__ hs, const float* __restrict__ wt,
    const float* __restrict__ qb, const float* __restrict__ kb, const float* __restrict__ vb,
    float* __restrict__ qp, float* __restrict__ kp, float* __restrict__ vp)
{
    extern __shared__ float sm[];
    float* As = sm;               // [2][128][36]
    float* Bs = sm + 2 * BUFF;    // [2][128][36]

    const int which = blockIdx.z >> 2, g = blockIdx.z & 3;
    const int m0 = blockIdx.y * 128, n0 = blockIdx.x * 128;
    const int tid = threadIdx.x, lane = tid & 31, wid = tid >> 5;
    const int wm = wid & 1, wn = wid >> 1;
    const int gq = lane >> 2, tg = lane & 3;

    const float* Ag = hs + (size_t)g * MPG * NC + (size_t)m0 * NC;
    const float* Bg = wt + (size_t)(which * 4 + g) * NC * NC + (size_t)n0 * NC;
    const float* bg = (which == 0 ? qb : which == 1 ? kb : vb) + (size_t)g * NC;
    float*       op = (which == 0 ? qp : which == 1 ? kp : vp);

    float acc[4][4][4];
    #pragma unroll
    for (int i = 0; i < 4; i++)
        #pragma unroll
        for (int j = 0; j < 4; j++)
            #pragma unroll
            for (int q = 0; q < 4; q++) acc[i][j][q] = 0.f;

    const int lr = tid >> 3;
    const int lc = (tid & 7) * 4;

    float4 pa[4], pb[4];
    // prologue: chunk 0 -> regs -> buf0; chunk 1 -> regs
    #pragma unroll
    for (int i = 0; i < 4; i++) {
        pa[i] = *(const float4*)(Ag + (size_t)(i * 32 + lr) * NC + lc);
        pb[i] = *(const float4*)(Bg + (size_t)(i * 32 + lr) * NC + lc);
    }
    #pragma unroll
    for (int i = 0; i < 4; i++) {
        float* as = As + (i * 32 + lr) * APAD + lc;
        float* bs = Bs + (i * 32 + lr) * APAD + lc;
        as[0] = tf(pa[i].x); as[1] = tf(pa[i].y); as[2] = tf(pa[i].z); as[3] = tf(pa[i].w);
        bs[0] = tf(pb[i].x); bs[1] = tf(pb[i].y); bs[2] = tf(pb[i].z); bs[3] = tf(pb[i].w);
    }
    #pragma unroll
    for (int i = 0; i < 4; i++) {
        pa[i] = *(const float4*)(Ag + (size_t)(i * 32 + lr) * NC + 32 + lc);
        pb[i] = *(const float4*)(Bg + (size_t)(i * 32 + lr) * NC + 32 + lc);
    }
    __syncthreads();

    const int NCH = NC / 32;      // 24
    for (int c = 0; c < NCH; c++) {
        const int buf = c & 1;
        // store chunk c+1 (in regs) into the other buffer, then refill regs
        if (c + 1 < NCH) {
            const int nb = buf ^ 1;
            #pragma unroll
            for (int i = 0; i < 4; i++) {
                float* as = As + nb * BUFF + (i * 32 + lr) * APAD + lc;
                float* bs = Bs + nb * BUFF + (i * 32 + lr) * APAD + lc;
                as[0] = tf(pa[i].x); as[1] = tf(pa[i].y); as[2] = tf(pa[i].z); as[3] = tf(pa[i].w);
                bs[0] = tf(pb[i].x); bs[1] = tf(pb[i].y); bs[2] = tf(pb[i].z); bs[3] = tf(pb[i].w);
            }
        }
        if (c + 2 < NCH) {
            const int kc = (c + 2) * 32;
            #pragma unroll
            for (int i = 0; i < 4; i++) {
                pa[i] = *(const float4*)(Ag + (size_t)(i * 32 + lr) * NC + kc + lc);
                pb[i] = *(const float4*)(Bg + (size_t)(i * 32 + lr) * NC + kc + lc);
            }
        }
        // compute chunk c
        {
            const float* Ab = As + buf * BUFF + (wm * 64) * APAD;
            const float* Bb = Bs + buf * BUFF + (wn * 32) * APAD;
            #pragma unroll
            for (int ks = 0; ks < 4; ks++) {
                const int kk = ks * 8;
                uint32_t af[4][4], bf[4][2];
                #pragma unroll
                for (int mt = 0; mt < 4; mt++) {
                    const float* ap = Ab + (mt * 16 + gq) * APAD + kk + tg;
                    af[mt][0] = __float_as_uint(ap[0]);
                    af[mt][1] = __float_as_uint(ap[8 * APAD]);
                    af[mt][2] = __float_as_uint(ap[4]);
                    af[mt][3] = __float_as_uint(ap[8 * APAD + 4]);
                }
                #pragma unroll
                for (int nt = 0; nt < 4; nt++) {
                    const float* bp = Bb + (nt * 8 + gq) * APAD + kk + tg;
                    bf[nt][0] = __float_as_uint(bp[0]);
                    bf[nt][1] = __float_as_uint(bp[4]);
                }
                #pragma unroll
                for (int mt = 0; mt < 4; mt++)
                    #pragma unroll
                    for (int nt = 0; nt < 4; nt++)
                        mma_tf32(acc[mt][nt], af[mt], bf[nt]);
            }
        }
        __syncthreads();
    }

    #pragma unroll
    for (int mt = 0; mt < 4; mt++) {
        const int row0 = m0 + wm * 64 + mt * 16 + gq;
        #pragma unroll
        for (int half = 0; half < 2; half++) {
            const int trow = row0 + half * 8;
            const int b = trow >> 9, l = trow & 511;
            #pragma unroll
            for (int nt = 0; nt < 4; nt++) {
                const int col = n0 + wn * 32 + nt * 8 + 2 * tg;
                const int h = col >> 6, dh = col & 63;
                const float2 bv = *(const float2*)(bg + col);
                float2 o;
                o.x = acc[mt][nt][half * 2 + 0] + bv.x;
                o.y = acc[mt][nt][half * 2 + 1] + bv.y;
                *(float2*)(op + ((((size_t)g * NB + b) * NH + h) * LQ + l) * DH + dh) = o;
            }
        }
    }
}

// ---------------------------------------------------------------------------
// Resident-KV flash attention, tf32 mma.sync. One CTA per (gbh, 32 queries).
// 256 threads (8 warps). Warp w owns keys [w*64, w*64+64).
// Scores/exp stay in registers; P -> A-fragment via intra-quad shuffles.
// smem: Qs[32][68] | mask[512] | wmax[8][32] | wsum[8][32] | inv[32] |
//       KV[512][72] (K phase uses stride 68; Cred[8][32][68] aliases KV)
// ---------------------------------------------------------------------------
#define QT   32
#define QP   68
#define KSTR 68
#define VSTR 72
#define CRS  68
#define SM_MSK  (QT*QP)             // 2176
#define SM_WMAX (SM_MSK + 512)      // 2688
#define SM_WSUM (SM_WMAX + 256)     // 2944
#define SM_INV  (SM_WSUM + 256)     // 3200
#define SM_KV   (SM_INV + 32)       // 3232
#define AFL_TOT (SM_KV + 512*VSTR)  // 40096 floats = 160384 B

// Build A-fragment (rows gq/gq+8, k cols tg/tg+4) from a C-fragment held in
// quad lanes: element (r, c) lives in lane (r-quad, c>>1) at index c&1.
__device__ __forceinline__ void p_relayout(const float c[4], uint32_t a[4],
                                           int lane, int tg) {
    const int src1 = (lane & ~3) | (tg >> 1);
    const int src2 = src1 + 2;
    const bool odd = (tg & 1);
    float x0 = __shfl_sync(0xFFFFFFFFu, c[0], src1);
    float x1 = __shfl_sync(0xFFFFFFFFu, c[1], src1);
    a[0] = __float_as_uint(odd ? x1 : x0);
    float y0 = __shfl_sync(0xFFFFFFFFu, c[2], src1);
    float y1 = __shfl_sync(0xFFFFFFFFu, c[3], src1);
    a[1] = __float_as_uint(odd ? y1 : y0);
    x0 = __shfl_sync(0xFFFFFFFFu, c[0], src2);
    x1 = __shfl_sync(0xFFFFFFFFu, c[1], src2);
    a[2] = __float_as_uint(odd ? x1 : x0);
    y0 = __shfl_sync(0xFFFFFFFFu, c[2], src2);
    y1 = __shfl_sync(0xFFFFFFFFu, c[3], src2);
    a[3] = __float_as_uint(odd ? y1 : y0);
}

__global__ __launch_bounds__(256, 1) void attn_flash_kernel(
    const float* __restrict__ qg, const float* __restrict__ kg,
    const float* __restrict__ vg, const float* __restrict__ mask,
    float* __restrict__ out)
{
    extern __shared__ float sm[];
    float* Qs   = sm;
    float* Msk  = sm + SM_MSK;
    float* Wmax = sm + SM_WMAX;
    float* Wsum = sm + SM_WSUM;
    float* Invs = sm + SM_INV;
    float* KV   = sm + SM_KV;
    float* Cred = KV;                 // alias (used after V is dead)

    const int gbh = blockIdx.y;
    const int l0  = blockIdx.x * QT;
    const int h   = gbh % NH;
    const int gb  = gbh / NH;
    const int tid  = threadIdx.x;
    const int lane = tid & 31;
    const int wid  = tid >> 5;
    const int gq = lane >> 2, tg = lane & 3;

    const float* Q  = qg + (size_t)gbh * LQ * DH;
    const float* K  = kg + (size_t)gbh * LQ * DH;
    const float* V  = vg + (size_t)gbh * LQ * DH;
    const float* mk = mask + (size_t)gb * LQ;

    // ---- loads: Q tile, mask row, full K (stride 68) ----
    #pragma unroll
    for (int i = 0; i < 2; i++) {
        const int idx = i * 256 + tid;
        const int row = idx >> 4, c4 = (idx & 15) * 4;
        const float4 v = *(const float4*)(Q + (size_t)(l0 + row) * DH + c4);
        float* qs = Qs + row * QP + c4;
        qs[0] = tf(v.x); qs[1] = tf(v.y); qs[2] = tf(v.z); qs[3] = tf(v.w);
    }
    Msk[tid] = mk[tid];
    Msk[tid + 256] = mk[tid + 256];
    #pragma unroll
    for (int i = 0; i < 16; i++) {
        const int idx = i * 256 + tid;
        const int r = idx >> 3, c8 = (idx & 7) * 8;
        const float4 a = *(const float4*)(K + (size_t)r * DH + c8);
        const float4 b = *(const float4*)(K + (size_t)r * DH + c8 + 4);
        float* ks = KV + r * KSTR + c8;
        ks[0] = tf(a.x); ks[1] = tf(a.y); ks[2] = tf(a.z); ks[3] = tf(a.w);
        ks[4] = tf(b.x); ks[5] = tf(b.y); ks[6] = tf(b.z); ks[7] = tf(b.w);
    }
    __syncthreads();   // S1

    // ---- Q fragments to registers ----
    uint32_t qf[2][8][4];
    #pragma unroll
    for (int ks = 0; ks < 8; ks++) {
        const int kk = ks * 8;
        #pragma unroll
        for (int mt = 0; mt < 2; mt++) {
            const float* ap = Qs + (mt * 16 + gq) * QP + kk + tg;
            qf[mt][ks][0] = __float_as_uint(ap[0]);
            qf[mt][ks][1] = __float_as_uint(ap[8 * QP]);
            qf[mt][ks][2] = __float_as_uint(ap[4]);
            qf[mt][ks][3] = __float_as_uint(ap[8 * QP + 4]);
        }
    }

    // ---- phase 1: S (32 x 64 per warp) in registers ----
    float sacc[2][8][4];
    #pragma unroll
    for (int mt = 0; mt < 2; mt++)
        #pragma unroll
        for (int nt = 0; nt < 8; nt++)
            #pragma unroll
            for (int q = 0; q < 4; q++) sacc[mt][nt][q] = 0.f;

    const float* Kb = KV + wid * 64 * KSTR;
    #pragma unroll
    for (int ks = 0; ks < 8; ks++) {
        const int kk = ks * 8;
        #pragma unroll
        for (int nt = 0; nt < 8; nt++) {
            uint32_t bf[2];
            const float* bp = Kb + (nt * 8 + gq) * KSTR + kk + tg;
            bf[0] = __float_as_uint(bp[0]);
            bf[1] = __float_as_uint(bp[4]);
            mma_tf32(sacc[0][nt], qf[0][ks], bf);
            mma_tf32(sacc[1][nt], qf[1][ks], bf);
        }
    }

    // ---- scale + mask + local row max ----
    const float scale = 0.125f;
    float lm[2][2];
    lm[0][0] = lm[0][1] = lm[1][0] = lm[1][1] = -1e30f;
    #pragma unroll
    for (int mt = 0; mt < 2; mt++)
        #pragma unroll
        for (int nt = 0; nt < 8; nt++) {
            const int col = wid * 64 + nt * 8 + 2 * tg;
            const float m0v = Msk[col], m1v = Msk[col + 1];
            float* s = sacc[mt][nt];
            s[0] = fmaf(s[0], scale, m0v);
            s[1] = fmaf(s[1], scale, m1v);
            s[2] = fmaf(s[2], scale, m0v);
            s[3] = fmaf(s[3], scale, m1v);
            lm[mt][0] = fmaxf(lm[mt][0], fmaxf(s[0], s[1]));
            lm[mt][1] = fmaxf(lm[mt][1], fmaxf(s[2], s[3]));
        }
    #pragma unroll
    for (int mt = 0; mt < 2; mt++)
        #pragma unroll
        for (int hf = 0; hf < 2; hf++) {
            float m = lm[mt][hf];
            m = fmaxf(m, __shfl_xor_sync(0xFFFFFFFFu, m, 1));
            m = fmaxf(m, __shfl_xor_sync(0xFFFFFFFFu, m, 2));
            lm[mt][hf] = m;
        }
    if (tg == 0) {
        Wmax[wid * 32 + gq]      = lm[0][0];
        Wmax[wid * 32 + gq + 8]  = lm[0][1];
        Wmax[wid * 32 + gq + 16] = lm[1][0];
        Wmax[wid * 32 + gq + 24] = lm[1][1];
    }
    __syncthreads();   // S2

    // ---- global max, exp in regs, local sum ----
    float gmax[2][2];
    #pragma unroll
    for (int mt = 0; mt < 2; mt++)
        #pragma unroll
        for (int hf = 0; hf < 2; hf++) {
            const int r = mt * 16 + gq + hf * 8;
            float m = -1e30f;
            #pragma unroll
            for (int w = 0; w < 8; w++) m = fmaxf(m, Wmax[w * 32 + r]);
            gmax[mt][hf] = m;
        }
    float ls[2][2] = {{0.f, 0.f}, {0.f, 0.f}};
    #pragma unroll
    for (int mt = 0; mt < 2; mt++)
        #pragma unroll
        for (int nt = 0; nt < 8; nt++) {
            float* s = sacc[mt][nt];
            float e0 = fast_exp(s[0] - gmax[mt][0]);
            float e1 = fast_exp(s[1] - gmax[mt][0]);
            float e2 = fast_exp(s[2] - gmax[mt][1]);
            float e3 = fast_exp(s[3] - gmax[mt][1]);
            ls[mt][0] += e0 + e1;
            ls[mt][1] += e2 + e3;
            s[0] = tf(e0); s[1] = tf(e1); s[2] = tf(e2); s[3] = tf(e3);
        }
    #pragma unroll
    for (int mt = 0; mt < 2; mt++)
        #pragma unroll
        for (int hf = 0; hf < 2; hf++) {
            float v = ls[mt][hf];
            v += __shfl_xor_sync(0xFFFFFFFFu, v, 1);
            v += __shfl_xor_sync(0xFFFFFFFFu, v, 2);
            ls[mt][hf] = v;
        }
    if (tg == 0) {
        Wsum[wid * 32 + gq]      = ls[0][0];
        Wsum[wid * 32 + gq + 8]  = ls[0][1];
        Wsum[wid * 32 + gq + 16] = ls[1][0];
        Wsum[wid * 32 + gq + 24] = ls[1][1];
    }

    // ---- V load (stride 72) overlaps the tail of softmax ----
    #pragma unroll
    for (int i = 0; i < 16; i++) {
        const int idx = i * 256 + tid;
        const int r = idx >> 3, c8 = (idx & 7) * 8;
        const float4 a = *(const float4*)(V + (size_t)r * DH + c8);
        const float4 b = *(const float4*)(V + (size_t)r * DH + c8 + 4);
        float* vs = KV + r * VSTR + c8;
        vs[0] = tf(a.x); vs[1] = tf(a.y); vs[2] = tf(a.z); vs[3] = tf(a.w);
        vs[4] = tf(b.x); vs[5] = tf(b.y); vs[6] = tf(b.z); vs[7] = tf(b.w);
    }
    __syncthreads();   // S3 (covers Wsum + V)

    if (wid == 0 && tg == 0) {
        #pragma unroll
        for (int j = 0; j < 4; j++) {
            const int r = j * 8 + gq;
            float ssum = 0.f;
            #pragma unroll
            for (int w = 0; w < 8; w++) ssum += Wsum[w * 32 + r];
            Invs[r] = 1.0f / ssum;
        }
    }

    // ---- phase 3: ctx_w = P_w @ V_w (per-warp 64-key strip) ----
    float ctx[2][8][4];
    #pragma unroll
    for (int mt = 0; mt < 2; mt++)
        #pragma unroll
        for (int nt = 0; nt < 8; nt++)
            #pragma unroll
            for (int q = 0; q < 4; q++) ctx[mt][nt][q] = 0.f;

    const float* Vb = KV + wid * 64 * VSTR;
    #pragma unroll
    for (int nt = 0; nt < 8; nt++) {          // k-tiles over this warp's 64 keys
        uint32_t vbf[8][2];
        #pragma unroll
        for (int ntd = 0; ntd < 8; ntd++) {
            vbf[ntd][0] = __float_as_uint(Vb[(nt * 8 + tg) * VSTR + ntd * 8 + gq]);
            vbf[ntd][1] = __float_as_uint(Vb[(nt * 8 + tg + 4) * VSTR + ntd * 8 + gq]);
        }
        uint32_t a0[4], a1[4];
        p_relayout(sacc[0][nt], a0, lane, tg);
        p_relayout(sacc[1][nt], a1, lane, tg);
        #pragma unroll
        for (int ntd = 0; ntd < 8; ntd++) {
            mma_tf32(ctx[0][ntd], a0, vbf[ntd]);
            mma_tf32(ctx[1][ntd], a1, vbf[ntd]);
        }
    }
    __syncthreads();   // S4: all V reads done; Invs published

    // ---- cross-warp ctx reduce through smem (aliased over KV) ----
    float* Cw = Cred + wid * 32 * CRS;
    #pragma unroll
    for (int mt = 0; mt < 2; mt++)
        #pragma unroll
        for (int ntd = 0; ntd < 8; ntd++) {
            *(float2*)(Cw + (mt * 16 + gq) * CRS + ntd * 8 + 2 * tg) =
                make_float2(ctx[mt][ntd][0], ctx[mt][ntd][1]);
            *(float2*)(Cw + (mt * 16 + gq + 8) * CRS + ntd * 8 + 2 * tg) =
                make_float2(ctx[mt][ntd][2], ctx[mt][ntd][3]);
        }
    __syncthreads();   // S5

    {
        const int row = tid & 31, c8 = (tid >> 5) * 8;
        float4 s0 = make_float4(0.f, 0.f, 0.f, 0.f);
        float4 s1 = make_float4(0.f, 0.f, 0.f, 0.f);
        #pragma unroll
        for (int w = 0; w < 8; w++) {
            const float* p = Cred + w * 32 * CRS + row * CRS + c8;
            const float4 t0 = *(const float4*)(p);
            const float4 t1 = *(const float4*)(p + 4);
            s0.x += t0.x; s0.y += t0.y; s0.z += t0.z; s0.w += t0.w;
            s1.x += t1.x; s1.y += t1.y; s1.z += t1.z; s1.w += t1.w;
        }
        const float iv = Invs[row];
        float* orow = out + ((size_t)gb * LQ + l0 + row) * NC + h * DH + c8;
        *(float4*)(orow)     = make_float4(s0.x * iv, s0.y * iv, s0.z * iv, s0.w * iv);
        *(float4*)(orow + 4) = make_float4(s1.x * iv, s1.y * iv, s1.z * iv, s1.w * iv);
    }
}

// ---------------------------------------------------------------------------
extern "C" void kernel_launch(void* const* d_in, const int* in_sizes, int n_in,
                              void* d_out, int out_size)
{
    (void)in_sizes; (void)n_in; (void)out_size;
    const float* hs   = (const float*)d_in[0];
    const float* mask = (const float*)d_in[1];
    const float* qw   = (const float*)d_in[2];
    const float* qb   = (const float*)d_in[3];
    const float* kw   = (const float*)d_in[4];
    const float* kb   = (const float*)d_in[5];
    const float* vw   = (const float*)d_in[6];
    const float* vb   = (const float*)d_in[7];
    float* out = (float*)d_out;

    float *qp, *kp, *vp, *wtp;
    cudaGetSymbolAddress((void**)&qp, g_q);
    cudaGetSymbolAddress((void**)&kp, g_k);
    cudaGetSymbolAddress((void**)&vp, g_v);
    cudaGetSymbolAddress((void**)&wtp, g_wt);

    dim3 tgrid(NC / 32, NC / 32, 12);
    wt_transpose_kernel<<<tgrid, dim3(32, 8)>>>(qw, kw, vw, wtp);

    const int gsmem = 4 * BUFF * (int)sizeof(float);   // 73728
    cudaFuncSetAttribute(qkv_mma_kernel,
                         cudaFuncAttributeMaxDynamicSharedMemorySize, gsmem);
    dim3 ggrid(NC / 128, MPG / 128, 12);
    qkv_mma_kernel<<<ggrid, 256, gsmem>>>(hs, wtp, qb, kb, vb, qp, kp, vp);

    const int asmem = AFL_TOT * (int)sizeof(float);    // 160384
    cudaFuncSetAttribute(attn_flash_kernel,
                         cudaFuncAttributeMaxDynamicSharedMemorySize, asmem);
    dim3 agrid(LQ / QT, NG * NB * NH);
    attn_flash_kernel<<<agrid, 256, asmem>>>(qp, kp, vp, mask, out);
}